// round 5
// baseline (speedup 1.0000x reference)
#include <cuda_runtime.h>
#include <cuda_bf16.h>
#include <math.h>
#include <stdint.h>

#define N_NODES_C 100000
#define N_EDGES_C 1000000
#define DIM 64          // NODE_DIM
#define EDIM 32         // EDGE_DIM
#define NGAUSS 16
#define HID 128
#define NLAYERS 4
#define CATD 160        // 2*DIM + EDIM
#define NGRAPHS 64

#define TILE_E 64
#define XP 164          // padded X row pitch (floats), 16B-aligned rows
#define HP 132          // padded H row pitch (floats), 16B-aligned rows
#define LYR_THREADS 512
#define LYR_GRID 148

// ---- scratch (static device globals; no allocation allowed) ----
__device__ __align__(256) float g_h[N_NODES_C * DIM];
__device__ __align__(256) float g_agg[N_NODES_C * DIM];
__device__ __align__(256) float g_ea[(size_t)N_EDGES_C * EDIM];
__device__ __align__(256) float g_pool[NGRAPHS * DIM];
__device__ __align__(256) float g_cnt[NGRAPHS];

// shared floats: W1 + W2 + b1 + b2 + X + H, plus dst/src ints
#define SMEM_FLOATS (CATD*HID + HID*DIM + HID + DIM + TILE_E*XP + TILE_E*HP)
#define SMEM_BYTES  (SMEM_FLOATS*4 + 2*TILE_E*4)

// ---- packed f32x2 helpers (sm_103a) ----
#define FFMA2(acc, a, b) \
    asm volatile("fma.rn.f32x2 %0, %1, %2, %0;" : "+l"(acc) : "l"(a), "l"(b))
#define PACK2(out, lo, hi) \
    asm("mov.b64 %0, {%1, %2};" : "=l"(out) : "r"(__float_as_uint(lo)), "r"(__float_as_uint(hi)))
#define UNPACK2(lo, hi, in) do { unsigned _ulo, _uhi; \
    asm("mov.b64 {%0, %1}, %2;" : "=r"(_ulo), "=r"(_uhi) : "l"(in)); \
    lo = __uint_as_float(_ulo); hi = __uint_as_float(_uhi); } while (0)

__device__ __forceinline__ void red_add_v4(float* p, float x, float y, float z, float w) {
    asm volatile("red.global.add.v4.f32 [%0], {%1,%2,%3,%4};"
                 :: "l"(p), "f"(x), "f"(y), "f"(z), "f"(w) : "memory");
}

// ---------------- init: h = embed[atoms], agg = 0 ----------------
__global__ void k_init_nodes(const int* __restrict__ atoms, const float* __restrict__ emb) {
    int i = blockIdx.x * blockDim.x + threadIdx.x;
    if (i < N_NODES_C * DIM) {
        int n = i >> 6, d = i & 63;
        g_h[i] = emb[atoms[n] * DIM + d];
        g_agg[i] = 0.0f;
    }
}

__global__ void k_zero_pool() {
    int i = blockIdx.x * blockDim.x + threadIdx.x;
    if (i < NGRAPHS * DIM) g_pool[i] = 0.0f;
    if (i < NGRAPHS) g_cnt[i] = 0.0f;
}

// ---------------- edge attributes: RBF(dist) ++ subunit embed ----------------
__global__ void k_edge_attr(const int* __restrict__ ei,
                            const float* __restrict__ coords,
                            const int* __restrict__ isrec,
                            const float* __restrict__ sub) {
    int e = blockIdx.x * blockDim.x + threadIdx.x;
    if (e >= N_EDGES_C) return;
    int s = ei[e];
    int t = ei[N_EDGES_C + e];
    float dx = coords[s*3+0] - coords[t*3+0];
    float dy = coords[s*3+1] - coords[t*3+1];
    float dz = coords[s*3+2] - coords[t*3+2];
    float dist = sqrtf(dx*dx + dy*dy + dz*dz);
    const float coeff = -4.5f;  // -0.5 / (5/15)^2
    float* row = g_ea + (size_t)e * EDIM;
    #pragma unroll
    for (int g = 0; g < NGAUSS; g++) {
        float off = 5.0f * (float)g * (1.0f / 15.0f);
        float d0 = dist - off;
        row[g] = __expf(coeff * d0 * d0);
    }
    int kind = (isrec[s] != isrec[t]) ? 1 : 0;
    #pragma unroll
    for (int g = 0; g < NGAUSS; g++) row[NGAUSS + g] = sub[kind * NGAUSS + g];
}

// ---------------- fused per-layer edge MLP + scatter-add ----------------
extern __shared__ float smem[];

__global__ __launch_bounds__(LYR_THREADS, 1)
void k_layer(const int* __restrict__ ei,
             const float* __restrict__ W1, const float* __restrict__ b1,
             const float* __restrict__ W2, const float* __restrict__ b2) {
    float* sW1 = smem;                        // [160][128]
    float* sW2 = sW1 + CATD * HID;            // [128][64]
    float* sB1 = sW2 + HID * DIM;             // [128]
    float* sB2 = sB1 + HID;                   // [64]
    float* sX  = sB2 + DIM;                   // [64][XP]
    float* sH  = sX + TILE_E * XP;            // [64][HP]
    int*  sDst = (int*)(sH + TILE_E * HP);    // [64]
    int*  sSrc = sDst + TILE_E;               // [64]

    const int tid = threadIdx.x;

    for (int i = tid; i < CATD * HID; i += LYR_THREADS) sW1[i] = W1[i];
    for (int i = tid; i < HID * DIM; i += LYR_THREADS)  sW2[i] = W2[i];
    if (tid < HID) sB1[tid] = b1[tid];
    if (tid < DIM) sB2[tid] = b2[tid];
    __syncthreads();

    const int* src = ei;
    const int* dst = ei + N_EDGES_C;
    const int tx = tid & 15;   // 16 col groups
    const int ty = tid >> 4;   // 32 row groups (2 rows each)
    const int NT = N_EDGES_C / TILE_E;

    // bias pairs held in registers across tiles
    unsigned long long bias1[4], bias2[2];
    #pragma unroll
    for (int j = 0; j < 4; j++) PACK2(bias1[j], sB1[tx*8 + 2*j], sB1[tx*8 + 2*j + 1]);
    #pragma unroll
    for (int j = 0; j < 2; j++) PACK2(bias2[j], sB2[tx*4 + 2*j], sB2[tx*4 + 2*j + 1]);

    for (int tile = blockIdx.x; tile < NT; tile += gridDim.x) {
        const int e0 = tile * TILE_E;

        // ---- stage indices
        if (tid < TILE_E) sDst[tid] = dst[e0 + tid];
        else if (tid < 2 * TILE_E) sSrc[tid - TILE_E] = src[e0 + tid - TILE_E];
        __syncthreads();

        // ---- gather X rows: [h[dst] | h[src] | edge_attr], float4 granularity
        // 64 edges x 40 float4 = 2560 items, 5 per thread
        #pragma unroll
        for (int t = tid; t < TILE_E * 40; t += LYR_THREADS) {
            int e = t / 40, q = t - e * 40;
            const float4* p;
            if (q < 16)        p = (const float4*)(g_h  + (size_t)sDst[e] * DIM) + q;
            else if (q < 32)   p = (const float4*)(g_h  + (size_t)sSrc[e] * DIM) + (q - 16);
            else               p = (const float4*)(g_ea + (size_t)(e0 + e) * EDIM) + (q - 32);
            *(float4*)&sX[e * XP + q * 4] = *p;
        }
        __syncthreads();

        // ---- GEMM1: [64,160] x [160,128], thread tile 2 rows x 8 cols, f32x2
        unsigned long long acc[2][4];
        #pragma unroll
        for (int i = 0; i < 2; i++)
            #pragma unroll
            for (int j = 0; j < 4; j++) acc[i][j] = bias1[j];

        {
            const float* xrow0 = sX + (ty * 2) * XP;
            const float* xrow1 = xrow0 + XP;
            const float* wcol = sW1 + tx * 8;
            #pragma unroll 2
            for (int k4 = 0; k4 < CATD; k4 += 4) {
                float4 a0 = *(const float4*)(xrow0 + k4);
                float4 a1 = *(const float4*)(xrow1 + k4);
                #pragma unroll
                for (int kk = 0; kk < 4; kk++) {
                    float s0 = (&a0.x)[kk];
                    float s1 = (&a1.x)[kk];
                    unsigned long long p0, p1;
                    PACK2(p0, s0, s0);
                    PACK2(p1, s1, s1);
                    const float* wk = wcol + (k4 + kk) * HID;
                    ulonglong2 wA = *(const ulonglong2*)(wk);      // cols 0..3
                    ulonglong2 wB = *(const ulonglong2*)(wk + 4);  // cols 4..7
                    FFMA2(acc[0][0], p0, wA.x);
                    FFMA2(acc[0][1], p0, wA.y);
                    FFMA2(acc[0][2], p0, wB.x);
                    FFMA2(acc[0][3], p0, wB.y);
                    FFMA2(acc[1][0], p1, wA.x);
                    FFMA2(acc[1][1], p1, wA.y);
                    FFMA2(acc[1][2], p1, wB.x);
                    FFMA2(acc[1][3], p1, wB.y);
                }
            }
        }
        // silu -> sH
        #pragma unroll
        for (int i = 0; i < 2; i++) {
            float* hrow = sH + (ty * 2 + i) * HP + tx * 8;
            #pragma unroll
            for (int j = 0; j < 4; j++) {
                float v0, v1;
                UNPACK2(v0, v1, acc[i][j]);
                v0 = v0 / (1.0f + __expf(-v0));
                v1 = v1 / (1.0f + __expf(-v1));
                *(float2*)(hrow + 2*j) = make_float2(v0, v1);
            }
        }
        __syncthreads();

        // ---- GEMM2: [64,128] x [128,64], thread tile 2 rows x 4 cols, f32x2
        unsigned long long acc2[2][2];
        acc2[0][0] = bias2[0]; acc2[0][1] = bias2[1];
        acc2[1][0] = bias2[0]; acc2[1][1] = bias2[1];
        {
            const float* hrow0 = sH + (ty * 2) * HP;
            const float* hrow1 = hrow0 + HP;
            const float* w2col = sW2 + tx * 4;
            #pragma unroll 2
            for (int k4 = 0; k4 < HID; k4 += 4) {
                float4 a0 = *(const float4*)(hrow0 + k4);
                float4 a1 = *(const float4*)(hrow1 + k4);
                #pragma unroll
                for (int kk = 0; kk < 4; kk++) {
                    float s0 = (&a0.x)[kk];
                    float s1 = (&a1.x)[kk];
                    unsigned long long p0, p1;
                    PACK2(p0, s0, s0);
                    PACK2(p1, s1, s1);
                    ulonglong2 w = *(const ulonglong2*)(w2col + (k4 + kk) * DIM);
                    FFMA2(acc2[0][0], p0, w.x);
                    FFMA2(acc2[0][1], p0, w.y);
                    FFMA2(acc2[1][0], p1, w.x);
                    FFMA2(acc2[1][1], p1, w.y);
                }
            }
        }
        #pragma unroll
        for (int i = 0; i < 2; i++) {
            int e = ty * 2 + i;
            float v0, v1, v2, v3;
            UNPACK2(v0, v1, acc2[i][0]);
            UNPACK2(v2, v3, acc2[i][1]);
            float* p = g_agg + (size_t)sDst[e] * DIM + tx * 4;
            red_add_v4(p, v0, v1, v2, v3);
        }
        __syncthreads();
    }
}

// ---------------- h = relu(h + agg); agg = 0 ----------------
__global__ void k_update() {
    int i = blockIdx.x * blockDim.x + threadIdx.x;
    if (i < N_NODES_C * DIM) {
        float v = g_h[i] + g_agg[i];
        g_h[i] = v > 0.0f ? v : 0.0f;
        g_agg[i] = 0.0f;
    }
}

// ---------------- pooling (segment sums + counts) ----------------
__global__ void k_pool(const int* __restrict__ batch) {
    int n = blockIdx.x * blockDim.x + threadIdx.x;
    if (n >= N_NODES_C) return;
    int b = batch[n];
    const float4* hp = (const float4*)(g_h + (size_t)n * DIM);
    float* pp = g_pool + b * DIM;
    #pragma unroll
    for (int q = 0; q < 16; q++) {
        float4 v = hp[q];
        red_add_v4(pp + q * 4, v.x, v.y, v.z, v.w);
    }
    atomicAdd(&g_cnt[b], 1.0f);
}

// ---------------- final FC ----------------
__global__ void k_final(const float* __restrict__ fcw, const float* __restrict__ fcb,
                        float* __restrict__ out) {
    int g = threadIdx.x;
    if (g < NGRAPHS) {
        float c = fmaxf(g_cnt[g], 1.0f);
        float inv = 1.0f / c;
        float s = 0.0f;
        #pragma unroll
        for (int d = 0; d < DIM; d++) s += (g_pool[g * DIM + d] * inv) * fcw[d];
        out[g] = s + fcb[0];
    }
}

extern "C" void kernel_launch(void* const* d_in, const int* in_sizes, int n_in,
                              void* d_out, int out_size) {
    const int*   atoms  = (const int*)d_in[0];
    const int*   ei     = (const int*)d_in[1];   // [2, E]: src row then dst row
    const float* coords = (const float*)d_in[2];
    const int*   isrec  = (const int*)d_in[3];
    const int*   batch  = (const int*)d_in[4];
    const float* emb    = (const float*)d_in[5];
    const float* sub    = (const float*)d_in[6];
    const float* W1     = (const float*)d_in[7]; // [4,160,128]
    const float* b1     = (const float*)d_in[8]; // [4,128]
    const float* W2     = (const float*)d_in[9]; // [4,128,64]
    const float* b2     = (const float*)d_in[10];// [4,64]
    const float* fcw    = (const float*)d_in[11];// [64,1]
    const float* fcb    = (const float*)d_in[12];// [1]
    float* out = (float*)d_out;

    cudaFuncSetAttribute(k_layer, cudaFuncAttributeMaxDynamicSharedMemorySize, SMEM_BYTES);

    k_init_nodes<<<(N_NODES_C * DIM + 255) / 256, 256>>>(atoms, emb);
    k_zero_pool<<<16, 256>>>();
    k_edge_attr<<<(N_EDGES_C + 255) / 256, 256>>>(ei, coords, isrec, sub);

    for (int l = 0; l < NLAYERS; l++) {
        k_layer<<<LYR_GRID, LYR_THREADS, SMEM_BYTES>>>(
            ei, W1 + (size_t)l * CATD * HID, b1 + (size_t)l * HID,
            W2 + (size_t)l * HID * DIM, b2 + (size_t)l * DIM);
        k_update<<<(N_NODES_C * DIM + 255) / 256, 256>>>();
    }

    k_pool<<<(N_NODES_C + 255) / 256, 256>>>(batch);
    k_final<<<1, 64>>>(fcw, fcb, out);
}

// round 9
// speedup vs baseline: 2.1129x; 2.1129x over previous
#include <cuda_runtime.h>
#include <cuda_fp16.h>
#include <math.h>
#include <stdint.h>

#define N_NODES_C 100000
#define N_EDGES_C 1000000
#define DIM 64          // NODE_DIM
#define EDIM 32         // EDGE_DIM
#define NGAUSS 16
#define HID 128
#define NLAYERS 4
#define CATD 160        // 2*DIM + EDIM
#define KPAD 192        // CATD padded to 12 k16 fragments
#define NGRAPHS 64

#define TILE_E 128
#define LYR_THREADS 256
#define LYR_GRID 148
#define NT_CEIL ((N_EDGES_C + TILE_E - 1) / TILE_E)

#define XPITCH 200      // fp16 elems per row (400B; 400 mod 128 = 16 -> ldmatrix conflict-free)
#define HPITCH 136      // fp16 elems per row (272B; 272 mod 128 = 16 -> conflict-free)

// ---- scratch (static device globals; no allocation allowed) ----
__device__ __align__(256) float g_h[N_NODES_C * DIM];
__device__ __align__(256) float g_agg[N_NODES_C * DIM];
__device__ __align__(256) __half g_hb[N_NODES_C * DIM];          // fp16 mirror of h
__device__ __align__(256) __half g_eb[(size_t)N_EDGES_C * EDIM]; // fp16 edge attrs
__device__ __align__(256) float g_pool[NGRAPHS * DIM];
__device__ __align__(256) float g_cnt[NGRAPHS];

// ---- smem layout (bytes) ----
#define OFF_X    0                          // [128][XPITCH] f16 = 51200
#define OFF_W1H  51200                      // [128 n][XPITCH k] f16 = 51200
#define OFF_W1L  102400                     // [128 n][XPITCH k] f16 = 51200
#define OFF_A2   153600                     // [128][HPITCH] f16 = 34816
#define OFF_W2H  188416                     // [64 n][HPITCH k] f16 = 17408
#define OFF_W2L  205824                     // [64 n][HPITCH k] f16 = 17408
#define OFF_B1   223232                     // 128 fp32
#define OFF_B2   223744                     // 64 fp32
#define OFF_DST  224000                     // 128 int
#define OFF_SRC  224512                     // 128 int
#define SMEM_TOTAL 225024

__device__ __forceinline__ uint32_t smem_u32(const void* p) {
    uint32_t a;
    asm("{ .reg .u64 t; cvta.to.shared.u64 t, %1; cvt.u32.u64 %0, t; }" : "=r"(a) : "l"(p));
    return a;
}

#define LDSM_X4(r0, r1, r2, r3, addr) \
    asm volatile("ldmatrix.sync.aligned.m8n8.x4.shared.b16 {%0,%1,%2,%3}, [%4];" \
                 : "=r"(r0), "=r"(r1), "=r"(r2), "=r"(r3) : "r"(addr))

#define LDSM_X2(r0, r1, addr) \
    asm volatile("ldmatrix.sync.aligned.m8n8.x2.shared.b16 {%0,%1}, [%2];" \
                 : "=r"(r0), "=r"(r1) : "r"(addr))

#define MMA_F16(c0, c1, c2, c3, a0, a1, a2, a3, b0, b1) \
    asm volatile("mma.sync.aligned.m16n8k16.row.col.f32.f16.f16.f32 " \
                 "{%0,%1,%2,%3}, {%4,%5,%6,%7}, {%8,%9}, {%0,%1,%2,%3};" \
                 : "+f"(c0), "+f"(c1), "+f"(c2), "+f"(c3) \
                 : "r"(a0), "r"(a1), "r"(a2), "r"(a3), "r"(b0), "r"(b1))

#define CVT_F16X2(res, lo, hi) \
    asm("cvt.rn.f16x2.f32 %0, %1, %2;" : "=r"(res) : "f"(hi), "f"(lo))

__device__ __forceinline__ void red_add_v4(float* p, float x, float y, float z, float w) {
    asm volatile("red.global.add.v4.f32 [%0], {%1,%2,%3,%4};"
                 :: "l"(p), "f"(x), "f"(y), "f"(z), "f"(w) : "memory");
}
__device__ __forceinline__ void red_add_v2(float* p, float x, float y) {
    asm volatile("red.global.add.v2.f32 [%0], {%1,%2};"
                 :: "l"(p), "f"(x), "f"(y) : "memory");
}

// ---------------- init: h = embed[atoms] (fp32 + fp16 mirror), agg = 0 ----------------
__global__ void k_init_nodes(const int* __restrict__ atoms, const float* __restrict__ emb) {
    int i = blockIdx.x * blockDim.x + threadIdx.x;
    if (i < N_NODES_C * DIM) {
        int n = i >> 6, d = i & 63;
        float v = emb[atoms[n] * DIM + d];
        g_h[i] = v;
        g_hb[i] = __float2half_rn(v);
        g_agg[i] = 0.0f;
    }
}

__global__ void k_zero_pool() {
    int i = blockIdx.x * blockDim.x + threadIdx.x;
    if (i < NGRAPHS * DIM) g_pool[i] = 0.0f;
    if (i < NGRAPHS) g_cnt[i] = 0.0f;
}

// ---------------- edge attributes (fp16): RBF(dist) ++ subunit embed ----------------
__global__ void k_edge_attr(const int* __restrict__ ei,
                            const float* __restrict__ coords,
                            const int* __restrict__ isrec,
                            const float* __restrict__ sub) {
    int e = blockIdx.x * blockDim.x + threadIdx.x;
    if (e >= N_EDGES_C) return;
    int s = ei[e];
    int t = ei[N_EDGES_C + e];
    float dx = coords[s*3+0] - coords[t*3+0];
    float dy = coords[s*3+1] - coords[t*3+1];
    float dz = coords[s*3+2] - coords[t*3+2];
    float dist = sqrtf(dx*dx + dy*dy + dz*dz);
    const float coeff = -4.5f;  // -0.5 / (5/15)^2
    __half* row = g_eb + (size_t)e * EDIM;
    #pragma unroll
    for (int g = 0; g < NGAUSS; g++) {
        float off = 5.0f * (float)g * (1.0f / 15.0f);
        float d0 = dist - off;
        row[g] = __float2half_rn(__expf(coeff * d0 * d0));
    }
    int kind = (isrec[s] != isrec[t]) ? 1 : 0;
    #pragma unroll
    for (int g = 0; g < NGAUSS; g++) row[NGAUSS + g] = __float2half_rn(sub[kind * NGAUSS + g]);
}

// ---------------- fused per-layer edge MLP (mma.sync f16, split weights) ----------------
extern __shared__ char lsm[];

__global__ __launch_bounds__(LYR_THREADS, 1)
void k_layer(const int* __restrict__ ei,
             const float* __restrict__ W1, const float* __restrict__ b1,
             const float* __restrict__ W2, const float* __restrict__ b2) {
    char* sm = lsm;
    const uint32_t sb = smem_u32(sm);
    const int tid = threadIdx.x;
    const int wid = tid >> 5;
    const int lane = tid & 31;

    float* sB1 = (float*)(sm + OFF_B1);
    float* sB2 = (float*)(sm + OFF_B2);
    int* sDst  = (int*)(sm + OFF_DST);
    int* sSrc  = (int*)(sm + OFF_SRC);

    // one-time: weights transposed -> smem fp16 hi/lo split, zero X (incl. k-pad), biases
    for (int i = tid; i < 128 * KPAD; i += LYR_THREADS) {
        int n = i / KPAD, k = i - n * KPAD;
        float v = (k < CATD) ? W1[k * HID + n] : 0.0f;
        __half hi = __float2half_rn(v);
        __half lo = __float2half_rn(v - __half2float(hi));
        *(__half*)(sm + OFF_W1H + (n * XPITCH + k) * 2) = hi;
        *(__half*)(sm + OFF_W1L + (n * XPITCH + k) * 2) = lo;
    }
    for (int i = tid; i < 64 * HID; i += LYR_THREADS) {
        int n = i >> 7, k = i & 127;
        float v = W2[k * DIM + n];
        __half hi = __float2half_rn(v);
        __half lo = __float2half_rn(v - __half2float(hi));
        *(__half*)(sm + OFF_W2H + (n * HPITCH + k) * 2) = hi;
        *(__half*)(sm + OFF_W2L + (n * HPITCH + k) * 2) = lo;
    }
    for (int i = tid; i < 128 * XPITCH * 2 / 4; i += LYR_THREADS) ((uint32_t*)(sm + OFF_X))[i] = 0;
    if (tid < HID) sB1[tid] = b1[tid];
    if (tid < DIM) sB2[tid] = b2[tid];
    __syncthreads();

    const int* src = ei;
    const int* dst = ei + N_EDGES_C;
    const int m0 = wid * 16;                      // warp's row strip
    // ldmatrix lane addressing components
    const int lr16 = lane & 15;                   // A-frag row within strip
    const int lc16 = (lane >> 4) * 8;             // A-frag k-halves
    const int lr8  = lane & 7;                    // B-frag n row
    const int lc8  = ((lane >> 3) & 1) * 8;       // B-frag k-halves
    const int qr   = lane >> 2;                   // c-frag row within 8
    const int qc   = (lane & 3) * 2;              // c-frag col pair base

    for (int tile = blockIdx.x; tile < NT_CEIL; tile += gridDim.x) {
        const int e0 = tile * TILE_E;
        const int valid = min(TILE_E, N_EDGES_C - e0);

        // ---- stage indices + gather X (fp16 rows: [h[dst] | h[src] | edge_attr]) ----
        if (tid < TILE_E && tid < valid) { sDst[tid] = dst[e0 + tid]; sSrc[tid] = src[e0 + tid]; }
        __syncthreads();
        #pragma unroll
        for (int t = tid; t < TILE_E * 40; t += LYR_THREADS) {
            int e = t / 40, q = t - e * 40;
            if (e < valid) {
                uint2 v; int kb;
                if (q < 16)      { v = *((const uint2*)(g_hb + (size_t)sDst[e] * DIM) + q); kb = q * 4; }
                else if (q < 32) { v = *((const uint2*)(g_hb + (size_t)sSrc[e] * DIM) + (q - 16)); kb = 64 + (q - 16) * 4; }
                else             { v = *((const uint2*)(g_eb + (size_t)(e0 + e) * EDIM) + (q - 32)); kb = 128 + (q - 32) * 4; }
                *(uint2*)(sm + OFF_X + (e * XPITCH + kb) * 2) = v;
            }
        }
        __syncthreads();

        // ---- GEMM1: D1[128,128] = X[128,192] @ (W1_hi + W1_lo); warp: 16 rows x 128 cols ----
        float acc[16][4];
        #pragma unroll
        for (int nf = 0; nf < 16; nf++)
            acc[nf][0] = acc[nf][1] = acc[nf][2] = acc[nf][3] = 0.0f;
        {
            // cache A fragments (12 kf x 4 regs), reuse across both weight halves
            uint32_t afr[12][4];
            const uint32_t xa = sb + OFF_X + ((m0 + lr16) * XPITCH + lc16) * 2;
            #pragma unroll
            for (int kf = 0; kf < 12; kf++)
                LDSM_X4(afr[kf][0], afr[kf][1], afr[kf][2], afr[kf][3], xa + kf * 32);
            #pragma unroll
            for (int half = 0; half < 2; half++) {
                const uint32_t wa = sb + (half ? OFF_W1L : OFF_W1H) + (lr8 * XPITCH + lc8) * 2;
                #pragma unroll
                for (int kf = 0; kf < 12; kf++) {
                    #pragma unroll
                    for (int nf = 0; nf < 16; nf++) {
                        uint32_t b0, b1;
                        LDSM_X2(b0, b1, wa + (nf * 8 * XPITCH + kf * 16) * 2);
                        MMA_F16(acc[nf][0], acc[nf][1], acc[nf][2], acc[nf][3],
                                afr[kf][0], afr[kf][1], afr[kf][2], afr[kf][3], b0, b1);
                    }
                }
            }
        }
        // ---- epilogue1: bias + silu -> A2 (fp16) ----
        {
            const int mlo = m0 + qr, mhi = mlo + 8;
            #pragma unroll
            for (int nf = 0; nf < 16; nf++) {
                int n = nf * 8 + qc;
                float blo = sB1[n], bhi = sB1[n + 1];
                float v0 = acc[nf][0] + blo, v1 = acc[nf][1] + bhi;
                float v2 = acc[nf][2] + blo, v3 = acc[nf][3] + bhi;
                v0 = v0 / (1.0f + __expf(-v0));
                v1 = v1 / (1.0f + __expf(-v1));
                v2 = v2 / (1.0f + __expf(-v2));
                v3 = v3 / (1.0f + __expf(-v3));
                uint32_t plo, phi;
                CVT_F16X2(plo, v0, v1);
                CVT_F16X2(phi, v2, v3);
                *(uint32_t*)(sm + OFF_A2 + (mlo * HPITCH + n) * 2) = plo;
                *(uint32_t*)(sm + OFF_A2 + (mhi * HPITCH + n) * 2) = phi;
            }
        }
        __syncthreads();

        // ---- GEMM2: D2[128,64] = A2[128,128] @ (W2_hi + W2_lo); warp: 16 rows x 64 cols ----
        float acc2[8][4];
        #pragma unroll
        for (int nf = 0; nf < 8; nf++)
            acc2[nf][0] = acc2[nf][1] = acc2[nf][2] = acc2[nf][3] = 0.0f;
        {
            uint32_t afr2[8][4];
            const uint32_t aa = sb + OFF_A2 + ((m0 + lr16) * HPITCH + lc16) * 2;
            #pragma unroll
            for (int kf = 0; kf < 8; kf++)
                LDSM_X4(afr2[kf][0], afr2[kf][1], afr2[kf][2], afr2[kf][3], aa + kf * 32);
            #pragma unroll
            for (int half = 0; half < 2; half++) {
                const uint32_t wa = sb + (half ? OFF_W2L : OFF_W2H) + (lr8 * HPITCH + lc8) * 2;
                #pragma unroll
                for (int kf = 0; kf < 8; kf++) {
                    #pragma unroll
                    for (int nf = 0; nf < 8; nf++) {
                        uint32_t b0, b1;
                        LDSM_X2(b0, b1, wa + (nf * 8 * HPITCH + kf * 16) * 2);
                        MMA_F16(acc2[nf][0], acc2[nf][1], acc2[nf][2], acc2[nf][3],
                                afr2[kf][0], afr2[kf][1], afr2[kf][2], afr2[kf][3], b0, b1);
                    }
                }
            }
        }
        // ---- epilogue2: bias + scatter-add ----
        {
            const int mlo = m0 + qr, mhi = mlo + 8;
            const bool vlo = mlo < valid, vhi = mhi < valid;
            float* plo = vlo ? (g_agg + (size_t)sDst[mlo] * DIM) : 0;
            float* phi = vhi ? (g_agg + (size_t)sDst[mhi] * DIM) : 0;
            #pragma unroll
            for (int nf = 0; nf < 8; nf++) {
                int n = nf * 8 + qc;
                float blo = sB2[n], bhi = sB2[n + 1];
                if (vlo) red_add_v2(plo + n, acc2[nf][0] + blo, acc2[nf][1] + bhi);
                if (vhi) red_add_v2(phi + n, acc2[nf][2] + blo, acc2[nf][3] + bhi);
            }
        }
        __syncthreads();
    }
}

// ---------------- h = relu(h + agg); agg = 0; refresh fp16 mirror ----------------
__global__ void k_update() {
    int i = blockIdx.x * blockDim.x + threadIdx.x;
    if (i < N_NODES_C * DIM) {
        float v = g_h[i] + g_agg[i];
        v = v > 0.0f ? v : 0.0f;
        g_h[i] = v;
        g_hb[i] = __float2half_rn(v);
        g_agg[i] = 0.0f;
    }
}

// ---------------- pooling (segment sums + counts) ----------------
__global__ void k_pool(const int* __restrict__ batch) {
    int n = blockIdx.x * blockDim.x + threadIdx.x;
    if (n >= N_NODES_C) return;
    int b = batch[n];
    const float4* hp = (const float4*)(g_h + (size_t)n * DIM);
    float* pp = g_pool + b * DIM;
    #pragma unroll
    for (int q = 0; q < 16; q++) {
        float4 v = hp[q];
        red_add_v4(pp + q * 4, v.x, v.y, v.z, v.w);
    }
    atomicAdd(&g_cnt[b], 1.0f);
}

// ---------------- final FC ----------------
__global__ void k_final(const float* __restrict__ fcw, const float* __restrict__ fcb,
                        float* __restrict__ out) {
    int g = threadIdx.x;
    if (g < NGRAPHS) {
        float c = fmaxf(g_cnt[g], 1.0f);
        float inv = 1.0f / c;
        float s = 0.0f;
        #pragma unroll
        for (int d = 0; d < DIM; d++) s += (g_pool[g * DIM + d] * inv) * fcw[d];
        out[g] = s + fcb[0];
    }
}

extern "C" void kernel_launch(void* const* d_in, const int* in_sizes, int n_in,
                              void* d_out, int out_size) {
    const int*   atoms  = (const int*)d_in[0];
    const int*   ei     = (const int*)d_in[1];   // [2, E]: src row then dst row
    const float* coords = (const float*)d_in[2];
    const int*   isrec  = (const int*)d_in[3];
    const int*   batch  = (const int*)d_in[4];
    const float* emb    = (const float*)d_in[5];
    const float* sub    = (const float*)d_in[6];
    const float* W1     = (const float*)d_in[7]; // [4,160,128]
    const float* b1     = (const float*)d_in[8]; // [4,128]
    const float* W2     = (const float*)d_in[9]; // [4,128,64]
    const float* b2     = (const float*)d_in[10];// [4,64]
    const float* fcw    = (const float*)d_in[11];// [64,1]
    const float* fcb    = (const float*)d_in[12];// [1]
    float* out = (float*)d_out;

    cudaFuncSetAttribute(k_layer, cudaFuncAttributeMaxDynamicSharedMemorySize, SMEM_TOTAL);

    k_init_nodes<<<(N_NODES_C * DIM + 255) / 256, 256>>>(atoms, emb);
    k_zero_pool<<<16, 256>>>();
    k_edge_attr<<<(N_EDGES_C + 255) / 256, 256>>>(ei, coords, isrec, sub);

    for (int l = 0; l < NLAYERS; l++) {
        k_layer<<<LYR_GRID, LYR_THREADS, SMEM_TOTAL>>>(
            ei, W1 + (size_t)l * CATD * HID, b1 + (size_t)l * HID,
            W2 + (size_t)l * HID * DIM, b2 + (size_t)l * DIM);
        k_update<<<(N_NODES_C * DIM + 255) / 256, 256>>>();
    }

    k_pool<<<(N_NODES_C + 255) / 256, 256>>>(batch);
    k_final<<<1, 64>>>(fcw, fcb, out);
}

// round 10
// speedup vs baseline: 3.6615x; 1.7329x over previous
#include <cuda_runtime.h>
#include <cuda_fp16.h>
#include <math.h>
#include <stdint.h>

#define N_NODES_C 100000
#define N_EDGES_C 1000000
#define DIM 64          // NODE_DIM
#define EDIM 32         // EDGE_DIM
#define NGAUSS 16
#define HID 128
#define NLAYERS 4
#define CATD 160        // 2*DIM + EDIM
#define KPAD 192        // CATD padded to 12 k16 fragments
#define NGRAPHS 64

#define TILE_E 128
#define LYR_THREADS 512
#define LYR_GRID 148
#define NT_CEIL ((N_EDGES_C + TILE_E - 1) / TILE_E)
#define PF_N (TILE_E * 40 / LYR_THREADS)   // 10 uint2 per thread

#define XPITCH 200      // fp16 elems per row (400B; 400 mod 128 = 16 -> ldmatrix conflict-free)
#define HPITCH 136      // fp16 elems per row (272B; 272 mod 128 = 16 -> conflict-free)

// ---- scratch (static device globals; no allocation allowed) ----
__device__ __align__(256) float g_h[N_NODES_C * DIM];
__device__ __align__(256) float g_agg[N_NODES_C * DIM];
__device__ __align__(256) __half g_hb[N_NODES_C * DIM];          // fp16 mirror of h
__device__ __align__(256) __half g_eb[(size_t)N_EDGES_C * EDIM]; // fp16 edge attrs
__device__ __align__(256) float g_pool[NGRAPHS * DIM];
__device__ __align__(256) float g_cnt[NGRAPHS];

// ---- smem layout (bytes) ----
#define OFF_X    0                          // [128][XPITCH] f16 = 51200
#define OFF_W1H  51200                      // [128 n][XPITCH k] f16 = 51200
#define OFF_W1L  102400                     // [128 n][XPITCH k] f16 = 51200
#define OFF_A2   153600                     // [128][HPITCH] f16 = 34816
#define OFF_W2H  188416                     // [64 n][HPITCH k] f16 = 17408
#define OFF_W2L  205824                     // [64 n][HPITCH k] f16 = 17408
#define OFF_B1   223232                     // 128 fp32
#define OFF_B2   223744                     // 64 fp32
#define SMEM_TOTAL 224008

__device__ __forceinline__ uint32_t smem_u32(const void* p) {
    uint32_t a;
    asm("{ .reg .u64 t; cvta.to.shared.u64 t, %1; cvt.u32.u64 %0, t; }" : "=r"(a) : "l"(p));
    return a;
}

#define LDSM_X4(r0, r1, r2, r3, addr) \
    asm volatile("ldmatrix.sync.aligned.m8n8.x4.shared.b16 {%0,%1,%2,%3}, [%4];" \
                 : "=r"(r0), "=r"(r1), "=r"(r2), "=r"(r3) : "r"(addr))

#define LDSM_X2(r0, r1, addr) \
    asm volatile("ldmatrix.sync.aligned.m8n8.x2.shared.b16 {%0,%1}, [%2];" \
                 : "=r"(r0), "=r"(r1) : "r"(addr))

#define MMA_F16(c0, c1, c2, c3, a0, a1, a2, a3, b0, b1) \
    asm volatile("mma.sync.aligned.m16n8k16.row.col.f32.f16.f16.f32 " \
                 "{%0,%1,%2,%3}, {%4,%5,%6,%7}, {%8,%9}, {%0,%1,%2,%3};" \
                 : "+f"(c0), "+f"(c1), "+f"(c2), "+f"(c3) \
                 : "r"(a0), "r"(a1), "r"(a2), "r"(a3), "r"(b0), "r"(b1))

#define CVT_F16X2(res, lo, hi) \
    asm("cvt.rn.f16x2.f32 %0, %1, %2;" : "=r"(res) : "f"(hi), "f"(lo))

__device__ __forceinline__ void red_add_v4(float* p, float x, float y, float z, float w) {
    asm volatile("red.global.add.v4.f32 [%0], {%1,%2,%3,%4};"
                 :: "l"(p), "f"(x), "f"(y), "f"(z), "f"(w) : "memory");
}
__device__ __forceinline__ void red_add_v2(float* p, float x, float y) {
    asm volatile("red.global.add.v2.f32 [%0], {%1,%2};"
                 :: "l"(p), "f"(x), "f"(y) : "memory");
}

// ---------------- init: h = embed[atoms] (fp32 + fp16 mirror), agg = 0 ----------------
__global__ void k_init_nodes(const int* __restrict__ atoms, const float* __restrict__ emb) {
    int i = blockIdx.x * blockDim.x + threadIdx.x;
    if (i < N_NODES_C * DIM) {
        int n = i >> 6, d = i & 63;
        float v = emb[atoms[n] * DIM + d];
        g_h[i] = v;
        g_hb[i] = __float2half_rn(v);
        g_agg[i] = 0.0f;
    }
}

__global__ void k_zero_pool() {
    int i = blockIdx.x * blockDim.x + threadIdx.x;
    if (i < NGRAPHS * DIM) g_pool[i] = 0.0f;
    if (i < NGRAPHS) g_cnt[i] = 0.0f;
}

// ---------------- edge attributes (fp16): RBF(dist) ++ subunit embed ----------------
__global__ void k_edge_attr(const int* __restrict__ ei,
                            const float* __restrict__ coords,
                            const int* __restrict__ isrec,
                            const float* __restrict__ sub) {
    int e = blockIdx.x * blockDim.x + threadIdx.x;
    if (e >= N_EDGES_C) return;
    int s = ei[e];
    int t = ei[N_EDGES_C + e];
    float dx = coords[s*3+0] - coords[t*3+0];
    float dy = coords[s*3+1] - coords[t*3+1];
    float dz = coords[s*3+2] - coords[t*3+2];
    float dist = sqrtf(dx*dx + dy*dy + dz*dz);
    const float coeff = -4.5f;  // -0.5 / (5/15)^2
    __half* row = g_eb + (size_t)e * EDIM;
    #pragma unroll
    for (int g = 0; g < NGAUSS; g++) {
        float off = 5.0f * (float)g * (1.0f / 15.0f);
        float d0 = dist - off;
        row[g] = __float2half_rn(__expf(coeff * d0 * d0));
    }
    int kind = (isrec[s] != isrec[t]) ? 1 : 0;
    #pragma unroll
    for (int g = 0; g < NGAUSS; g++) row[NGAUSS + g] = __float2half_rn(sub[kind * NGAUSS + g]);
}

// ---------------- fused per-layer edge MLP (mma.sync f16, split weights, pipelined) ----
extern __shared__ char lsm[];

__global__ __launch_bounds__(LYR_THREADS, 1)
void k_layer(const int* __restrict__ ei,
             const float* __restrict__ W1, const float* __restrict__ b1,
             const float* __restrict__ W2, const float* __restrict__ b2) {
    char* sm = lsm;
    const uint32_t sb = smem_u32(sm);
    const int tid = threadIdx.x;
    const int wid = tid >> 5;
    const int lane = tid & 31;

    float* sB1 = (float*)(sm + OFF_B1);
    float* sB2 = (float*)(sm + OFF_B2);

    // one-time: weights transposed -> smem fp16 hi/lo split, zero X (incl. k-pad), biases
    for (int i = tid; i < 128 * KPAD; i += LYR_THREADS) {
        int n = i / KPAD, k = i - n * KPAD;
        float v = (k < CATD) ? W1[k * HID + n] : 0.0f;
        __half hi = __float2half_rn(v);
        __half lo = __float2half_rn(v - __half2float(hi));
        *(__half*)(sm + OFF_W1H + (n * XPITCH + k) * 2) = hi;
        *(__half*)(sm + OFF_W1L + (n * XPITCH + k) * 2) = lo;
    }
    for (int i = tid; i < 64 * HID; i += LYR_THREADS) {
        int n = i >> 7, k = i & 127;
        float v = W2[k * DIM + n];
        __half hi = __float2half_rn(v);
        __half lo = __float2half_rn(v - __half2float(hi));
        *(__half*)(sm + OFF_W2H + (n * HPITCH + k) * 2) = hi;
        *(__half*)(sm + OFF_W2L + (n * HPITCH + k) * 2) = lo;
    }
    for (int i = tid; i < 128 * XPITCH * 2 / 4; i += LYR_THREADS) ((uint32_t*)(sm + OFF_X))[i] = 0;
    if (tid < HID) sB1[tid] = b1[tid];
    if (tid < DIM) sB2[tid] = b2[tid];
    __syncthreads();

    const int* src = ei;
    const int* dst = ei + N_EDGES_C;

    // warp decomposition: 8 row strips x 2 column groups
    const int m0 = (wid & 7) * 16;
    const int cg = wid >> 3;          // 0 or 1
    // ldmatrix lane addressing components
    const int lr16 = lane & 15;
    const int lc16 = (lane >> 4) * 8;
    const int lr8  = lane & 7;
    const int lc8  = ((lane >> 3) & 1) * 8;
    const int qr   = lane >> 2;
    const int qc   = (lane & 3) * 2;

    // ---- prefetch helper state ----
    uint2 pf[PF_N];

    // prologue: prefetch + store tile0's X
    int tile = blockIdx.x;
    {
        int e0 = tile * TILE_E;
        int valid = (tile < NT_CEIL) ? min(TILE_E, N_EDGES_C - e0) : 0;
        #pragma unroll
        for (int k = 0; k < PF_N; k++) {
            int i = tid + k * LYR_THREADS;
            int e = i / 40, q = i - e * 40;
            if (e < valid) {
                if (q < 16)      pf[k] = *((const uint2*)(g_hb + (size_t)dst[e0 + e] * DIM) + q);
                else if (q < 32) pf[k] = *((const uint2*)(g_hb + (size_t)src[e0 + e] * DIM) + (q - 16));
                else             pf[k] = *((const uint2*)(g_eb + (size_t)(e0 + e) * EDIM) + (q - 32));
            }
        }
        #pragma unroll
        for (int k = 0; k < PF_N; k++) {
            int i = tid + k * LYR_THREADS;
            int e = i / 40, q = i - e * 40;
            if (e < valid) {
                int kb = (q < 16) ? q * 4 : (q < 32) ? 64 + (q - 16) * 4 : 128 + (q - 32) * 4;
                *(uint2*)(sm + OFF_X + (e * XPITCH + kb) * 2) = pf[k];
            }
        }
    }
    __syncthreads();

    for (; tile < NT_CEIL; tile += LYR_GRID) {
        const int e0 = tile * TILE_E;
        const int valid = min(TILE_E, N_EDGES_C - e0);
        const int tnext = tile + LYR_GRID;
        const int e0n = tnext * TILE_E;
        const int validn = (tnext < NT_CEIL) ? min(TILE_E, N_EDGES_C - e0n) : 0;

        // dst row indices for this tile's scatter (per-lane)
        const int mlo = m0 + qr, mhi = mlo + 8;
        const int dlo = (mlo < valid) ? dst[e0 + mlo] : 0;
        const int dhi = (mhi < valid) ? dst[e0 + mhi] : 0;

        // ---- issue prefetch LDGs for next tile (consumed after sync1) ----
        #pragma unroll
        for (int k = 0; k < PF_N; k++) {
            int i = tid + k * LYR_THREADS;
            int e = i / 40, q = i - e * 40;
            if (e < validn) {
                if (q < 16)      pf[k] = *((const uint2*)(g_hb + (size_t)dst[e0n + e] * DIM) + q);
                else if (q < 32) pf[k] = *((const uint2*)(g_hb + (size_t)src[e0n + e] * DIM) + (q - 16));
                else             pf[k] = *((const uint2*)(g_eb + (size_t)(e0n + e) * EDIM) + (q - 32));
            }
        }

        // ---- GEMM1: D1[128, cg*64..+64] = X[128,192] @ (W1_hi + W1_lo) ----
        float acc[8][4];
        #pragma unroll
        for (int nf = 0; nf < 8; nf++)
            acc[nf][0] = acc[nf][1] = acc[nf][2] = acc[nf][3] = 0.0f;
        {
            const uint32_t xa = sb + OFF_X + ((m0 + lr16) * XPITCH + lc16) * 2;
            #pragma unroll
            for (int half = 0; half < 2; half++) {
                const uint32_t wa = sb + (half ? OFF_W1L : OFF_W1H)
                                  + ((cg * 64 + lr8) * XPITCH + lc8) * 2;
                #pragma unroll
                for (int kf = 0; kf < 12; kf++) {
                    uint32_t a0, a1, a2, a3;
                    LDSM_X4(a0, a1, a2, a3, xa + kf * 32);
                    #pragma unroll
                    for (int nf = 0; nf < 8; nf++) {
                        uint32_t b0, b1;
                        LDSM_X2(b0, b1, wa + (nf * 8 * XPITCH + kf * 16) * 2);
                        MMA_F16(acc[nf][0], acc[nf][1], acc[nf][2], acc[nf][3],
                                a0, a1, a2, a3, b0, b1);
                    }
                }
            }
        }
        // ---- epilogue1: bias + silu -> A2 (fp16) ----
        #pragma unroll
        for (int nf = 0; nf < 8; nf++) {
            int n = cg * 64 + nf * 8 + qc;
            float blo = sB1[n], bhi = sB1[n + 1];
            float v0 = acc[nf][0] + blo, v1 = acc[nf][1] + bhi;
            float v2 = acc[nf][2] + blo, v3 = acc[nf][3] + bhi;
            v0 = v0 / (1.0f + __expf(-v0));
            v1 = v1 / (1.0f + __expf(-v1));
            v2 = v2 / (1.0f + __expf(-v2));
            v3 = v3 / (1.0f + __expf(-v3));
            uint32_t plo, phi;
            CVT_F16X2(plo, v0, v1);
            CVT_F16X2(phi, v2, v3);
            *(uint32_t*)(sm + OFF_A2 + ((m0 + qr) * HPITCH + n) * 2) = plo;
            *(uint32_t*)(sm + OFF_A2 + ((m0 + qr + 8) * HPITCH + n) * 2) = phi;
        }
        __syncthreads();   // A2 ready; X fully consumed

        // ---- store prefetched data -> X (for next tile) ----
        #pragma unroll
        for (int k = 0; k < PF_N; k++) {
            int i = tid + k * LYR_THREADS;
            int e = i / 40, q = i - e * 40;
            if (e < validn) {
                int kb = (q < 16) ? q * 4 : (q < 32) ? 64 + (q - 16) * 4 : 128 + (q - 32) * 4;
                *(uint2*)(sm + OFF_X + (e * XPITCH + kb) * 2) = pf[k];
            }
        }

        // ---- GEMM2: D2[128, cg*32..+32] = A2[128,128] @ (W2_hi + W2_lo) ----
        float acc2[4][4];
        #pragma unroll
        for (int nf = 0; nf < 4; nf++)
            acc2[nf][0] = acc2[nf][1] = acc2[nf][2] = acc2[nf][3] = 0.0f;
        {
            const uint32_t aa = sb + OFF_A2 + ((m0 + lr16) * HPITCH + lc16) * 2;
            #pragma unroll
            for (int half = 0; half < 2; half++) {
                const uint32_t wa = sb + (half ? OFF_W2L : OFF_W2H)
                                  + ((cg * 32 + lr8) * HPITCH + lc8) * 2;
                #pragma unroll
                for (int kf = 0; kf < 8; kf++) {
                    uint32_t a0, a1, a2, a3;
                    LDSM_X4(a0, a1, a2, a3, aa + kf * 32);
                    #pragma unroll
                    for (int nf = 0; nf < 4; nf++) {
                        uint32_t b0, b1;
                        LDSM_X2(b0, b1, wa + (nf * 8 * HPITCH + kf * 16) * 2);
                        MMA_F16(acc2[nf][0], acc2[nf][1], acc2[nf][2], acc2[nf][3],
                                a0, a1, a2, a3, b0, b1);
                    }
                }
            }
        }
        // ---- epilogue2: bias + scatter-add ----
        {
            const bool vlo = mlo < valid, vhi = mhi < valid;
            float* plo = g_agg + (size_t)dlo * DIM;
            float* phi = g_agg + (size_t)dhi * DIM;
            #pragma unroll
            for (int nf = 0; nf < 4; nf++) {
                int n = cg * 32 + nf * 8 + qc;
                float blo = sB2[n], bhi = sB2[n + 1];
                if (vlo) red_add_v2(plo + n, acc2[nf][0] + blo, acc2[nf][1] + bhi);
                if (vhi) red_add_v2(phi + n, acc2[nf][2] + blo, acc2[nf][3] + bhi);
            }
        }
        __syncthreads();   // X(t+1) visible; A2 free
    }
}

// ---------------- h = relu(h + agg); agg = 0; refresh fp16 mirror ----------------
__global__ void k_update() {
    int i = blockIdx.x * blockDim.x + threadIdx.x;
    if (i < N_NODES_C * DIM) {
        float v = g_h[i] + g_agg[i];
        v = v > 0.0f ? v : 0.0f;
        g_h[i] = v;
        g_hb[i] = __float2half_rn(v);
        g_agg[i] = 0.0f;
    }
}

// ---------------- pooling (segment sums + counts) ----------------
__global__ void k_pool(const int* __restrict__ batch) {
    int n = blockIdx.x * blockDim.x + threadIdx.x;
    if (n >= N_NODES_C) return;
    int b = batch[n];
    const float4* hp = (const float4*)(g_h + (size_t)n * DIM);
    float* pp = g_pool + b * DIM;
    #pragma unroll
    for (int q = 0; q < 16; q++) {
        float4 v = hp[q];
        red_add_v4(pp + q * 4, v.x, v.y, v.z, v.w);
    }
    atomicAdd(&g_cnt[b], 1.0f);
}

// ---------------- final FC ----------------
__global__ void k_final(const float* __restrict__ fcw, const float* __restrict__ fcb,
                        float* __restrict__ out) {
    int g = threadIdx.x;
    if (g < NGRAPHS) {
        float c = fmaxf(g_cnt[g], 1.0f);
        float inv = 1.0f / c;
        float s = 0.0f;
        #pragma unroll
        for (int d = 0; d < DIM; d++) s += (g_pool[g * DIM + d] * inv) * fcw[d];
        out[g] = s + fcb[0];
    }
}

extern "C" void kernel_launch(void* const* d_in, const int* in_sizes, int n_in,
                              void* d_out, int out_size) {
    const int*   atoms  = (const int*)d_in[0];
    const int*   ei     = (const int*)d_in[1];   // [2, E]: src row then dst row
    const float* coords = (const float*)d_in[2];
    const int*   isrec  = (const int*)d_in[3];
    const int*   batch  = (const int*)d_in[4];
    const float* emb    = (const float*)d_in[5];
    const float* sub    = (const float*)d_in[6];
    const float* W1     = (const float*)d_in[7]; // [4,160,128]
    const float* b1     = (const float*)d_in[8]; // [4,128]
    const float* W2     = (const float*)d_in[9]; // [4,128,64]
    const float* b2     = (const float*)d_in[10];// [4,64]
    const float* fcw    = (const float*)d_in[11];// [64,1]
    const float* fcb    = (const float*)d_in[12];// [1]
    float* out = (float*)d_out;

    cudaFuncSetAttribute(k_layer, cudaFuncAttributeMaxDynamicSharedMemorySize, SMEM_TOTAL);

    k_init_nodes<<<(N_NODES_C * DIM + 255) / 256, 256>>>(atoms, emb);
    k_zero_pool<<<16, 256>>>();
    k_edge_attr<<<(N_EDGES_C + 255) / 256, 256>>>(ei, coords, isrec, sub);

    for (int l = 0; l < NLAYERS; l++) {
        k_layer<<<LYR_GRID, LYR_THREADS, SMEM_TOTAL>>>(
            ei, W1 + (size_t)l * CATD * HID, b1 + (size_t)l * HID,
            W2 + (size_t)l * HID * DIM, b2 + (size_t)l * DIM);
        k_update<<<(N_NODES_C * DIM + 255) / 256, 256>>>();
    }

    k_pool<<<(N_NODES_C + 255) / 256, 256>>>(batch);
    k_final<<<1, 64>>>(fcw, fcb, out);
}

// round 14
// speedup vs baseline: 6.2650x; 1.7110x over previous
#include <cuda_runtime.h>
#include <cuda_fp16.h>
#include <math.h>
#include <stdint.h>

#define N_NODES_C 100000
#define N_EDGES_C 1000000
#define DIM 64          // NODE_DIM
#define EDIM 32         // EDGE_DIM
#define NGAUSS 16
#define HID 128
#define NLAYERS 4
#define CATD 160        // 2*DIM + EDGE_DIM
#define NGRAPHS 64
#define UW 256          // U width (dst-half 0:128, src-half 128:256)

#define TILE_E 128
#define LYR_THREADS 512
#define LYR_GRID 148
#define NT_CEIL ((N_EDGES_C + TILE_E - 1) / TILE_E)
#define NP_TILES ((N_NODES_C + 127) / 128)

#define EPITCH 40       // sE/W1g pitch (80B)
#define HPITCH 136      // A2/W2 pitch (272B; conflict-free)
#define APITCH 72       // nodeprep pitch (144B; conflict-free)

// ---- scratch (static device globals; no allocation allowed) ----
__device__ __align__(256) float g_h[N_NODES_C * DIM];
__device__ __align__(256) float g_agg[N_NODES_C * DIM];
__device__ __align__(256) __half g_u[(size_t)N_NODES_C * UW];    // per-node W1 partials
__device__ __align__(256) __half g_eb[(size_t)N_EDGES_C * EDIM]; // fp16 edge attrs
__device__ __align__(256) float g_pool[NGRAPHS * DIM];
__device__ __align__(256) float g_cnt[NGRAPHS];

// ---- edge-kernel smem layout (bytes) ----
#define OFF_E    0                          // [128][EPITCH] f16 = 10240
#define OFF_WGH  10240                      // [128 n][EPITCH k] f16 = 10240
#define OFF_WGL  20480                      // 10240
#define OFF_A2   30720                      // [128][HPITCH] f16 = 34816
#define OFF_W2H  65536                      // [64 n][HPITCH k] f16 = 17408
#define OFF_W2L  82944                      // 17408
#define OFF_B1   100352                     // 128 fp32
#define OFF_B2   100864                     // 64 fp32
#define SMEM_EDGE 101120

// ---- nodeprep smem layout ----
#define NP_A     0                          // [128][APITCH] f16 = 18432
#define NP_BH    18432                      // [256 n][APITCH k] f16 = 36864
#define NP_BL    55296                      // 36864
#define SMEM_NP  92160

__device__ __forceinline__ uint32_t smem_u32(const void* p) {
    uint32_t a;
    asm("{ .reg .u64 t; cvta.to.shared.u64 t, %1; cvt.u32.u64 %0, t; }" : "=r"(a) : "l"(p));
    return a;
}

#define LDSM_X4(r0, r1, r2, r3, addr) \
    asm volatile("ldmatrix.sync.aligned.m8n8.x4.shared.b16 {%0,%1,%2,%3}, [%4];" \
                 : "=r"(r0), "=r"(r1), "=r"(r2), "=r"(r3) : "r"(addr))

#define LDSM_X2(r0, r1, addr) \
    asm volatile("ldmatrix.sync.aligned.m8n8.x2.shared.b16 {%0,%1}, [%2];" \
                 : "=r"(r0), "=r"(r1) : "r"(addr))

#define MMA_F16(c0, c1, c2, c3, a0, a1, a2, a3, b0, b1) \
    asm volatile("mma.sync.aligned.m16n8k16.row.col.f32.f16.f16.f32 " \
                 "{%0,%1,%2,%3}, {%4,%5,%6,%7}, {%8,%9}, {%0,%1,%2,%3};" \
                 : "+f"(c0), "+f"(c1), "+f"(c2), "+f"(c3) \
                 : "r"(a0), "r"(a1), "r"(a2), "r"(a3), "r"(b0), "r"(b1))

#define CVT_F16X2(res, lo, hi) \
    asm("cvt.rn.f16x2.f32 %0, %1, %2;" : "=r"(res) : "f"(hi), "f"(lo))

__device__ __forceinline__ void red_add_v4(float* p, float x, float y, float z, float w) {
    asm volatile("red.global.add.v4.f32 [%0], {%1,%2,%3,%4};"
                 :: "l"(p), "f"(x), "f"(y), "f"(z), "f"(w) : "memory");
}
__device__ __forceinline__ void red_add_v2(float* p, float x, float y) {
    asm volatile("red.global.add.v2.f32 [%0], {%1,%2};"
                 :: "l"(p), "f"(x), "f"(y) : "memory");
}

// ---------------- init: h = embed[atoms], agg = 0 ----------------
__global__ void k_init_nodes(const int* __restrict__ atoms, const float* __restrict__ emb) {
    int i = blockIdx.x * blockDim.x + threadIdx.x;
    if (i < N_NODES_C * DIM) {
        int n = i >> 6, d = i & 63;
        g_h[i] = emb[atoms[n] * DIM + d];
        g_agg[i] = 0.0f;
    }
}

__global__ void k_zero_pool() {
    int i = blockIdx.x * blockDim.x + threadIdx.x;
    if (i < NGRAPHS * DIM) g_pool[i] = 0.0f;
    if (i < NGRAPHS) g_cnt[i] = 0.0f;
}

// ---------------- edge attributes (fp16): RBF(dist) ++ subunit embed ----------------
__global__ void k_edge_attr(const int* __restrict__ ei,
                            const float* __restrict__ coords,
                            const int* __restrict__ isrec,
                            const float* __restrict__ sub) {
    int e = blockIdx.x * blockDim.x + threadIdx.x;
    if (e >= N_EDGES_C) return;
    int s = ei[e];
    int t = ei[N_EDGES_C + e];
    float dx = coords[s*3+0] - coords[t*3+0];
    float dy = coords[s*3+1] - coords[t*3+1];
    float dz = coords[s*3+2] - coords[t*3+2];
    float dist = sqrtf(dx*dx + dy*dy + dz*dz);
    const float coeff = -4.5f;  // -0.5 / (5/15)^2
    __half* row = g_eb + (size_t)e * EDIM;
    #pragma unroll
    for (int g = 0; g < NGAUSS; g++) {
        float off = 5.0f * (float)g * (1.0f / 15.0f);
        float d0 = dist - off;
        row[g] = __float2half_rn(__expf(coeff * d0 * d0));
    }
    int kind = (isrec[s] != isrec[t]) ? 1 : 0;
    #pragma unroll
    for (int g = 0; g < NGAUSS; g++) row[NGAUSS + g] = __float2half_rn(sub[kind * NGAUSS + g]);
}

// ---------------- nodeprep: (update h) + U = h @ [W1_dst | W1_src]  ----------------
extern __shared__ char npsm[];

__global__ __launch_bounds__(LYR_THREADS, 1)
void k_nodeprep(const float* __restrict__ W1, int do_update) {
    char* sm = npsm;
    const uint32_t sb = smem_u32(sm);
    const int tid = threadIdx.x;
    const int wid = tid >> 5;
    const int lane = tid & 31;

    // weights: B[n][k], n<128: W1[k][n]; n>=128: W1[64+k][n-128]; hi/lo split
    for (int i = tid; i < 256 * 64; i += LYR_THREADS) {
        int n = i >> 6, k = i & 63;
        float v = (n < 128) ? W1[k * HID + n] : W1[(64 + k) * HID + (n - 128)];
        __half hi = __float2half_rn(v);
        __half lo = __float2half_rn(v - __half2float(hi));
        *(__half*)(sm + NP_BH + (n * APITCH + k) * 2) = hi;
        *(__half*)(sm + NP_BL + (n * APITCH + k) * 2) = lo;
    }
    __syncthreads();

    const int m0 = (wid & 7) * 16;
    const int cgn = wid >> 3;      // 0/1: n cols cgn*128..+128
    const int lr16 = lane & 15;
    const int lc16 = (lane >> 4) * 8;
    const int lr8  = lane & 7;
    const int lc8  = ((lane >> 3) & 1) * 8;
    const int qr   = lane >> 2;
    const int qc   = (lane & 3) * 2;

    for (int tile = blockIdx.x; tile < NP_TILES; tile += LYR_GRID) {
        const int base = tile * 128;

        // load h rows (optionally fused relu update), fp16 -> smem A
        #pragma unroll
        for (int i4 = tid; i4 < 128 * 16; i4 += LYR_THREADS) {
            int r = i4 >> 4, c4 = (i4 & 15) * 4;
            int node = base + r;
            if (node < N_NODES_C) {
                float4 hv = *(const float4*)(g_h + (size_t)node * DIM + c4);
                if (do_update) {
                    float4 av = *(const float4*)(g_agg + (size_t)node * DIM + c4);
                    hv.x = fmaxf(hv.x + av.x, 0.0f);
                    hv.y = fmaxf(hv.y + av.y, 0.0f);
                    hv.z = fmaxf(hv.z + av.z, 0.0f);
                    hv.w = fmaxf(hv.w + av.w, 0.0f);
                    *(float4*)(g_h + (size_t)node * DIM + c4) = hv;
                    *(float4*)(g_agg + (size_t)node * DIM + c4) = make_float4(0.f, 0.f, 0.f, 0.f);
                }
                uint32_t p0, p1;
                CVT_F16X2(p0, hv.x, hv.y);
                CVT_F16X2(p1, hv.z, hv.w);
                *(uint32_t*)(sm + NP_A + (r * APITCH + c4) * 2) = p0;
                *(uint32_t*)(sm + NP_A + (r * APITCH + c4 + 2) * 2) = p1;
            }
        }
        __syncthreads();

        float acc[16][4];
        #pragma unroll
        for (int nf = 0; nf < 16; nf++)
            acc[nf][0] = acc[nf][1] = acc[nf][2] = acc[nf][3] = 0.0f;

        const uint32_t xa = sb + NP_A + ((m0 + lr16) * APITCH + lc16) * 2;
        #pragma unroll
        for (int half = 0; half < 2; half++) {
            const uint32_t wa = sb + (half ? NP_BL : NP_BH)
                              + ((cgn * 128 + lr8) * APITCH + lc8) * 2;
            #pragma unroll
            for (int kf = 0; kf < 4; kf++) {
                uint32_t a0, a1, a2, a3;
                LDSM_X4(a0, a1, a2, a3, xa + kf * 32);
                #pragma unroll
                for (int nf = 0; nf < 16; nf++) {
                    uint32_t b0, b1;
                    LDSM_X2(b0, b1, wa + (nf * 8 * APITCH + kf * 16) * 2);
                    MMA_F16(acc[nf][0], acc[nf][1], acc[nf][2], acc[nf][3],
                            a0, a1, a2, a3, b0, b1);
                }
            }
        }
        // store U (fp16)
        {
            int nlo = base + m0 + qr, nhi = nlo + 8;
            #pragma unroll
            for (int nf = 0; nf < 16; nf++) {
                int n = cgn * 128 + nf * 8 + qc;
                uint32_t plo, phi;
                CVT_F16X2(plo, acc[nf][0], acc[nf][1]);
                CVT_F16X2(phi, acc[nf][2], acc[nf][3]);
                if (nlo < N_NODES_C) *(uint32_t*)(g_u + (size_t)nlo * UW + n) = plo;
                if (nhi < N_NODES_C) *(uint32_t*)(g_u + (size_t)nhi * UW + n) = phi;
            }
        }
        __syncthreads();
    }
}

// ---------------- edge kernel: ea-GEMM + U-adds + silu + GEMM2 + scatter ----------------
extern __shared__ char lsm[];

__global__ __launch_bounds__(LYR_THREADS, 1)
void k_layer(const int* __restrict__ ei,
             const float* __restrict__ W1, const float* __restrict__ b1,
             const float* __restrict__ W2, const float* __restrict__ b2) {
    char* sm = lsm;
    const uint32_t sb = smem_u32(sm);
    const int tid = threadIdx.x;
    const int wid = tid >> 5;
    const int lane = tid & 31;

    float* sB1 = (float*)(sm + OFF_B1);
    float* sB2 = (float*)(sm + OFF_B2);

    // W1g = W1 rows 128..159 -> [128 n][EPITCH k], hi/lo
    for (int i = tid; i < 128 * EDIM; i += LYR_THREADS) {
        int n = i >> 5, k = i & 31;
        float v = W1[(128 + k) * HID + n];
        __half hi = __float2half_rn(v);
        __half lo = __float2half_rn(v - __half2float(hi));
        *(__half*)(sm + OFF_WGH + (n * EPITCH + k) * 2) = hi;
        *(__half*)(sm + OFF_WGL + (n * EPITCH + k) * 2) = lo;
    }
    // W2 -> [64 n][HPITCH k], hi/lo
    for (int i = tid; i < 64 * HID; i += LYR_THREADS) {
        int n = i >> 7, k = i & 127;
        float v = W2[k * DIM + n];
        __half hi = __float2half_rn(v);
        __half lo = __float2half_rn(v - __half2float(hi));
        *(__half*)(sm + OFF_W2H + (n * HPITCH + k) * 2) = hi;
        *(__half*)(sm + OFF_W2L + (n * HPITCH + k) * 2) = lo;
    }
    if (tid < HID) sB1[tid] = b1[tid];
    if (tid < DIM) sB2[tid] = b2[tid];

    const int* src = ei;
    const int* dst = ei + N_EDGES_C;

    const int m0 = (wid & 7) * 16;
    const int cg = wid >> 3;       // 0/1
    const int lr16 = lane & 15;
    const int lc16 = (lane >> 4) * 8;
    const int lr8  = lane & 7;
    const int lc8  = ((lane >> 3) & 1) * 8;
    const int qr   = lane >> 2;
    const int qc   = (lane & 3) * 2;

    // edge-attr staging role: 4 threads per edge, one uint4 (8 halves) each -> 32 halves/edge
    const int pe = tid >> 2;       // edge within tile (0..127)
    const int pq = tid & 3;        // quarter (k-halves pq*8 .. pq*8+7)

    // prologue: load tile0's edge attrs into sE
    int tile = blockIdx.x;
    {
        int e0 = tile * TILE_E;
        int valid = min(TILE_E, N_EDGES_C - e0);
        if (pe < valid) {
            uint4 v = *(const uint4*)(g_eb + (size_t)(e0 + pe) * EDIM + pq * 8);
            *(uint4*)(sm + OFF_E + (pe * EPITCH + pq * 8) * 2) = v;
        }
    }
    __syncthreads();

    for (; tile < NT_CEIL; tile += LYR_GRID) {
        const int e0 = tile * TILE_E;
        const int valid = min(TILE_E, N_EDGES_C - e0);
        const int tnext = tile + LYR_GRID;
        const int e0n = tnext * TILE_E;
        const int validn = (tnext < NT_CEIL) ? min(TILE_E, N_EDGES_C - e0n) : 0;

        // row indices for this thread's two rows
        const int mlo = m0 + qr, mhi = mlo + 8;
        const bool vlo = mlo < valid, vhi = mhi < valid;
        const int dlo = vlo ? dst[e0 + mlo] : 0;
        const int dhi = vhi ? dst[e0 + mhi] : 0;
        const int slo = vlo ? src[e0 + mlo] : 0;
        const int shi = vhi ? src[e0 + mhi] : 0;

        // ---- issue U gather loads (hidden under ea-GEMM) ----
        uint32_t ud0[8], ud1[8], us0[8], us1[8];
        {
            const __half* pd0 = g_u + (size_t)dlo * UW + cg * 64 + qc;
            const __half* pd1 = g_u + (size_t)dhi * UW + cg * 64 + qc;
            const __half* ps0 = g_u + (size_t)slo * UW + 128 + cg * 64 + qc;
            const __half* ps1 = g_u + (size_t)shi * UW + 128 + cg * 64 + qc;
            #pragma unroll
            for (int nf = 0; nf < 8; nf++) {
                ud0[nf] = *(const uint32_t*)(pd0 + nf * 8);
                ud1[nf] = *(const uint32_t*)(pd1 + nf * 8);
                us0[nf] = *(const uint32_t*)(ps0 + nf * 8);
                us1[nf] = *(const uint32_t*)(ps1 + nf * 8);
            }
        }

        // ---- prefetch next tile's edge attrs ----
        uint4 pfe;
        bool has_pfe = false;
        if (pe < validn) {
            pfe = *(const uint4*)(g_eb + (size_t)(e0n + pe) * EDIM + pq * 8);
            has_pfe = true;
        }

        // ---- ea-GEMM: acc[128, cg*64..+64] = sE[128,32] @ (W1g_hi + W1g_lo) ----
        float acc[8][4];
        #pragma unroll
        for (int nf = 0; nf < 8; nf++)
            acc[nf][0] = acc[nf][1] = acc[nf][2] = acc[nf][3] = 0.0f;
        {
            const uint32_t xa = sb + OFF_E + ((m0 + lr16) * EPITCH + lc16) * 2;
            #pragma unroll
            for (int half = 0; half < 2; half++) {
                const uint32_t wa = sb + (half ? OFF_WGL : OFF_WGH)
                                  + ((cg * 64 + lr8) * EPITCH + lc8) * 2;
                #pragma unroll
                for (int kf = 0; kf < 2; kf++) {
                    uint32_t a0, a1, a2, a3;
                    LDSM_X4(a0, a1, a2, a3, xa + kf * 32);
                    #pragma unroll
                    for (int nf = 0; nf < 8; nf++) {
                        uint32_t b0, b1;
                        LDSM_X2(b0, b1, wa + (nf * 8 * EPITCH + kf * 16) * 2);
                        MMA_F16(acc[nf][0], acc[nf][1], acc[nf][2], acc[nf][3],
                                a0, a1, a2, a3, b0, b1);
                    }
                }
            }
        }

        // ---- epilogue1: + u_dst + u_src + bias, silu -> A2 (fp16) ----
        #pragma unroll
        for (int nf = 0; nf < 8; nf++) {
            int n = cg * 64 + nf * 8 + qc;
            float blo = sB1[n], bhi = sB1[n + 1];
            float2 fd0 = __half22float2(*(__half2*)&ud0[nf]);
            float2 fs0 = __half22float2(*(__half2*)&us0[nf]);
            float2 fd1 = __half22float2(*(__half2*)&ud1[nf]);
            float2 fs1 = __half22float2(*(__half2*)&us1[nf]);
            float v0 = acc[nf][0] + fd0.x + fs0.x + blo;
            float v1 = acc[nf][1] + fd0.y + fs0.y + bhi;
            float v2 = acc[nf][2] + fd1.x + fs1.x + blo;
            float v3 = acc[nf][3] + fd1.y + fs1.y + bhi;
            v0 = v0 / (1.0f + __expf(-v0));
            v1 = v1 / (1.0f + __expf(-v1));
            v2 = v2 / (1.0f + __expf(-v2));
            v3 = v3 / (1.0f + __expf(-v3));
            uint32_t plo, phi;
            CVT_F16X2(plo, v0, v1);
            CVT_F16X2(phi, v2, v3);
            *(uint32_t*)(sm + OFF_A2 + (mlo * HPITCH + n) * 2) = plo;
            *(uint32_t*)(sm + OFF_A2 + (mhi * HPITCH + n) * 2) = phi;
        }
        __syncthreads();   // A2 ready; sE consumed

        // ---- store prefetched edge attrs -> sE (next tile) ----
        if (has_pfe)
            *(uint4*)(sm + OFF_E + (pe * EPITCH + pq * 8) * 2) = pfe;

        // ---- GEMM2: D2[128, cg*32..+32] = A2[128,128] @ (W2_hi + W2_lo) ----
        float acc2[4][4];
        #pragma unroll
        for (int nf = 0; nf < 4; nf++)
            acc2[nf][0] = acc2[nf][1] = acc2[nf][2] = acc2[nf][3] = 0.0f;
        {
            const uint32_t aa = sb + OFF_A2 + ((m0 + lr16) * HPITCH + lc16) * 2;
            #pragma unroll
            for (int half = 0; half < 2; half++) {
                const uint32_t wa = sb + (half ? OFF_W2L : OFF_W2H)
                                  + ((cg * 32 + lr8) * HPITCH + lc8) * 2;
                #pragma unroll
                for (int kf = 0; kf < 8; kf++) {
                    uint32_t a0, a1, a2, a3;
                    LDSM_X4(a0, a1, a2, a3, aa + kf * 32);
                    #pragma unroll
                    for (int nf = 0; nf < 4; nf++) {
                        uint32_t b0, b1;
                        LDSM_X2(b0, b1, wa + (nf * 8 * HPITCH + kf * 16) * 2);
                        MMA_F16(acc2[nf][0], acc2[nf][1], acc2[nf][2], acc2[nf][3],
                                a0, a1, a2, a3, b0, b1);
                    }
                }
            }
        }
        // ---- epilogue2: bias + scatter-add ----
        {
            float* plo = g_agg + (size_t)dlo * DIM;
            float* phi = g_agg + (size_t)dhi * DIM;
            #pragma unroll
            for (int nf = 0; nf < 4; nf++) {
                int n = cg * 32 + nf * 8 + qc;
                float blo = sB2[n], bhi = sB2[n + 1];
                if (vlo) red_add_v2(plo + n, acc2[nf][0] + blo, acc2[nf][1] + bhi);
                if (vhi) red_add_v2(phi + n, acc2[nf][2] + blo, acc2[nf][3] + bhi);
            }
        }
        __syncthreads();   // sE(next) visible; A2 free
    }
}

// ---------------- pooling (fused final relu update) ----------------
__global__ void k_pool(const int* __restrict__ batch) {
    int n = blockIdx.x * blockDim.x + threadIdx.x;
    if (n >= N_NODES_C) return;
    int b = batch[n];
    const float4* hp = (const float4*)(g_h + (size_t)n * DIM);
    const float4* ap = (const float4*)(g_agg + (size_t)n * DIM);
    float* pp = g_pool + b * DIM;
    #pragma unroll
    for (int q = 0; q < 16; q++) {
        float4 h = hp[q], a = ap[q];
        red_add_v4(pp + q * 4,
                   fmaxf(h.x + a.x, 0.0f), fmaxf(h.y + a.y, 0.0f),
                   fmaxf(h.z + a.z, 0.0f), fmaxf(h.w + a.w, 0.0f));
    }
    atomicAdd(&g_cnt[b], 1.0f);
}

// ---------------- final FC ----------------
__global__ void k_final(const float* __restrict__ fcw, const float* __restrict__ fcb,
                        float* __restrict__ out) {
    int g = threadIdx.x;
    if (g < NGRAPHS) {
        float c = fmaxf(g_cnt[g], 1.0f);
        float inv = 1.0f / c;
        float s = 0.0f;
        #pragma unroll
        for (int d = 0; d < DIM; d++) s += (g_pool[g * DIM + d] * inv) * fcw[d];
        out[g] = s + fcb[0];
    }
}

extern "C" void kernel_launch(void* const* d_in, const int* in_sizes, int n_in,
                              void* d_out, int out_size) {
    const int*   atoms  = (const int*)d_in[0];
    const int*   ei     = (const int*)d_in[1];   // [2, E]: src row then dst row
    const float* coords = (const float*)d_in[2];
    const int*   isrec  = (const int*)d_in[3];
    const int*   batch  = (const int*)d_in[4];
    const float* emb    = (const float*)d_in[5];
    const float* sub    = (const float*)d_in[6];
    const float* W1     = (const float*)d_in[7]; // [4,160,128]
    const float* b1     = (const float*)d_in[8]; // [4,128]
    const float* W2     = (const float*)d_in[9]; // [4,128,64]
    const float* b2     = (const float*)d_in[10];// [4,64]
    const float* fcw    = (const float*)d_in[11];// [64,1]
    const float* fcb    = (const float*)d_in[12];// [1]
    float* out = (float*)d_out;

    cudaFuncSetAttribute(k_layer, cudaFuncAttributeMaxDynamicSharedMemorySize, SMEM_EDGE);
    cudaFuncSetAttribute(k_nodeprep, cudaFuncAttributeMaxDynamicSharedMemorySize, SMEM_NP);

    k_init_nodes<<<(N_NODES_C * DIM + 255) / 256, 256>>>(atoms, emb);
    k_zero_pool<<<16, 256>>>();
    k_edge_attr<<<(N_EDGES_C + 255) / 256, 256>>>(ei, coords, isrec, sub);

    for (int l = 0; l < NLAYERS; l++) {
        k_nodeprep<<<LYR_GRID, LYR_THREADS, SMEM_NP>>>(W1 + (size_t)l * CATD * HID, l > 0);
        k_layer<<<LYR_GRID, LYR_THREADS, SMEM_EDGE>>>(
            ei, W1 + (size_t)l * CATD * HID, b1 + (size_t)l * HID,
            W2 + (size_t)l * HID * DIM, b2 + (size_t)l * DIM);
    }

    k_pool<<<(N_NODES_C + 255) / 256, 256>>>(batch);
    k_final<<<1, 64>>>(fcw, fcb, out);
}

// round 15
// speedup vs baseline: 7.8425x; 1.2518x over previous
#include <cuda_runtime.h>
#include <cuda_fp16.h>
#include <math.h>
#include <stdint.h>

#define N_NODES_C 100000
#define N_EDGES_C 1000000
#define DIM 64          // NODE_DIM
#define EDIM 32         // EDGE_DIM
#define NGAUSS 16
#define HID 128
#define NLAYERS 4
#define CATD 160        // 2*DIM + EDGE_DIM
#define NGRAPHS 64
#define UW 256          // U width (dst-half 0:128, src-half 128:256)

#define TILE_E 128
#define LYR_THREADS 512
#define LYR_GRID 148
#define NT_CEIL ((N_EDGES_C + TILE_E - 1) / TILE_E)
#define NP_TILES ((N_NODES_C + 127) / 128)

#define EPITCH 40       // sE/W1g pitch (80B)
#define HPITCH 136      // A2/W2 pitch (272B; conflict-free)
#define APITCH 72       // nodeprep pitch (144B; conflict-free)

// ---- scratch (static device globals; no allocation allowed) ----
__device__ __align__(256) float g_h[N_NODES_C * DIM];
__device__ __align__(256) float g_agg[N_NODES_C * DIM];
__device__ __align__(256) __half g_u[(size_t)N_NODES_C * UW];    // per-node W1 partials
__device__ __align__(256) __half g_eb[(size_t)N_EDGES_C * EDIM]; // fp16 edge attrs
__device__ __align__(256) float g_pool[NGRAPHS * DIM];
__device__ __align__(256) float g_cnt[NGRAPHS];

// ---- edge-kernel smem layout (bytes) ----
#define OFF_E    0                          // [128][EPITCH] f16 = 10240
#define OFF_WGH  10240                      // [128 n][EPITCH k] f16 = 10240
#define OFF_WGL  20480                      // 10240
#define OFF_A2   30720                      // [128][HPITCH] f16 = 34816
#define OFF_W2H  65536                      // [64 n][HPITCH k] f16 = 17408
#define OFF_W2L  82944                      // 17408
#define OFF_B1   100352                     // 128 fp32
#define OFF_B2   100864                     // 64 fp32
#define SMEM_EDGE 101120

// ---- nodeprep smem layout ----
#define NP_A     0                          // [128][APITCH] f16 = 18432
#define NP_BH    18432                      // [256 n][APITCH k] f16 = 36864
#define NP_BL    55296                      // 36864
#define SMEM_NP  92160

__device__ __forceinline__ uint32_t smem_u32(const void* p) {
    uint32_t a;
    asm("{ .reg .u64 t; cvta.to.shared.u64 t, %1; cvt.u32.u64 %0, t; }" : "=r"(a) : "l"(p));
    return a;
}

#define LDSM_X4(r0, r1, r2, r3, addr) \
    asm volatile("ldmatrix.sync.aligned.m8n8.x4.shared.b16 {%0,%1,%2,%3}, [%4];" \
                 : "=r"(r0), "=r"(r1), "=r"(r2), "=r"(r3) : "r"(addr))

#define LDSM_X2(r0, r1, addr) \
    asm volatile("ldmatrix.sync.aligned.m8n8.x2.shared.b16 {%0,%1}, [%2];" \
                 : "=r"(r0), "=r"(r1) : "r"(addr))

#define MMA_F16(c0, c1, c2, c3, a0, a1, a2, a3, b0, b1) \
    asm volatile("mma.sync.aligned.m16n8k16.row.col.f32.f16.f16.f32 " \
                 "{%0,%1,%2,%3}, {%4,%5,%6,%7}, {%8,%9}, {%0,%1,%2,%3};" \
                 : "+f"(c0), "+f"(c1), "+f"(c2), "+f"(c3) \
                 : "r"(a0), "r"(a1), "r"(a2), "r"(a3), "r"(b0), "r"(b1))

#define CVT_F16X2(res, lo, hi) \
    asm("cvt.rn.f16x2.f32 %0, %1, %2;" : "=r"(res) : "f"(hi), "f"(lo))

// pairwise named barrier: warps (q, cg=0) and (q, cg=1), 64 threads, ids 1..8
#define PAIR_BAR(q) \
    asm volatile("bar.sync %0, 64;" :: "r"(1 + (q)) : "memory")

__device__ __forceinline__ void red_add_v4(float* p, float x, float y, float z, float w) {
    asm volatile("red.global.add.v4.f32 [%0], {%1,%2,%3,%4};"
                 :: "l"(p), "f"(x), "f"(y), "f"(z), "f"(w) : "memory");
}
__device__ __forceinline__ void red_add_v2(float* p, float x, float y) {
    asm volatile("red.global.add.v2.f32 [%0], {%1,%2};"
                 :: "l"(p), "f"(x), "f"(y) : "memory");
}

// ---------------- init: h = embed[atoms], agg = 0 ----------------
__global__ void k_init_nodes(const int* __restrict__ atoms, const float* __restrict__ emb) {
    int i = blockIdx.x * blockDim.x + threadIdx.x;
    if (i < N_NODES_C * DIM) {
        int n = i >> 6, d = i & 63;
        g_h[i] = emb[atoms[n] * DIM + d];
        g_agg[i] = 0.0f;
    }
}

__global__ void k_zero_pool() {
    int i = blockIdx.x * blockDim.x + threadIdx.x;
    if (i < NGRAPHS * DIM) g_pool[i] = 0.0f;
    if (i < NGRAPHS) g_cnt[i] = 0.0f;
}

// ---------------- edge attributes (fp16): RBF(dist) ++ subunit embed ----------------
__global__ void k_edge_attr(const int* __restrict__ ei,
                            const float* __restrict__ coords,
                            const int* __restrict__ isrec,
                            const float* __restrict__ sub) {
    int e = blockIdx.x * blockDim.x + threadIdx.x;
    if (e >= N_EDGES_C) return;
    int s = ei[e];
    int t = ei[N_EDGES_C + e];
    float dx = coords[s*3+0] - coords[t*3+0];
    float dy = coords[s*3+1] - coords[t*3+1];
    float dz = coords[s*3+2] - coords[t*3+2];
    float dist = sqrtf(dx*dx + dy*dy + dz*dz);
    const float coeff = -4.5f;  // -0.5 / (5/15)^2
    __half* row = g_eb + (size_t)e * EDIM;
    #pragma unroll
    for (int g = 0; g < NGAUSS; g++) {
        float off = 5.0f * (float)g * (1.0f / 15.0f);
        float d0 = dist - off;
        row[g] = __float2half_rn(__expf(coeff * d0 * d0));
    }
    int kind = (isrec[s] != isrec[t]) ? 1 : 0;
    #pragma unroll
    for (int g = 0; g < NGAUSS; g++) row[NGAUSS + g] = __float2half_rn(sub[kind * NGAUSS + g]);
}

// ---------------- nodeprep: (update h) + U = h @ [W1_dst | W1_src]  ----------------
extern __shared__ char npsm[];

__global__ __launch_bounds__(LYR_THREADS, 1)
void k_nodeprep(const float* __restrict__ W1, int do_update) {
    char* sm = npsm;
    const uint32_t sb = smem_u32(sm);
    const int tid = threadIdx.x;
    const int wid = tid >> 5;
    const int lane = tid & 31;

    // weights: B[n][k], n<128: W1[k][n]; n>=128: W1[64+k][n-128]; hi/lo split
    for (int i = tid; i < 256 * 64; i += LYR_THREADS) {
        int n = i >> 6, k = i & 63;
        float v = (n < 128) ? W1[k * HID + n] : W1[(64 + k) * HID + (n - 128)];
        __half hi = __float2half_rn(v);
        __half lo = __float2half_rn(v - __half2float(hi));
        *(__half*)(sm + NP_BH + (n * APITCH + k) * 2) = hi;
        *(__half*)(sm + NP_BL + (n * APITCH + k) * 2) = lo;
    }
    __syncthreads();

    const int m0 = (wid & 7) * 16;
    const int cgn = wid >> 3;      // 0/1: n cols cgn*128..+128
    const int lr16 = lane & 15;
    const int lc16 = (lane >> 4) * 8;
    const int lr8  = lane & 7;
    const int lc8  = ((lane >> 3) & 1) * 8;
    const int qr   = lane >> 2;
    const int qc   = (lane & 3) * 2;

    for (int tile = blockIdx.x; tile < NP_TILES; tile += LYR_GRID) {
        const int base = tile * 128;

        // load h rows (optionally fused relu update), fp16 -> smem A
        #pragma unroll
        for (int i4 = tid; i4 < 128 * 16; i4 += LYR_THREADS) {
            int r = i4 >> 4, c4 = (i4 & 15) * 4;
            int node = base + r;
            if (node < N_NODES_C) {
                float4 hv = *(const float4*)(g_h + (size_t)node * DIM + c4);
                if (do_update) {
                    float4 av = *(const float4*)(g_agg + (size_t)node * DIM + c4);
                    hv.x = fmaxf(hv.x + av.x, 0.0f);
                    hv.y = fmaxf(hv.y + av.y, 0.0f);
                    hv.z = fmaxf(hv.z + av.z, 0.0f);
                    hv.w = fmaxf(hv.w + av.w, 0.0f);
                    *(float4*)(g_h + (size_t)node * DIM + c4) = hv;
                    *(float4*)(g_agg + (size_t)node * DIM + c4) = make_float4(0.f, 0.f, 0.f, 0.f);
                }
                uint32_t p0, p1;
                CVT_F16X2(p0, hv.x, hv.y);
                CVT_F16X2(p1, hv.z, hv.w);
                *(uint32_t*)(sm + NP_A + (r * APITCH + c4) * 2) = p0;
                *(uint32_t*)(sm + NP_A + (r * APITCH + c4 + 2) * 2) = p1;
            }
        }
        __syncthreads();

        float acc[16][4];
        #pragma unroll
        for (int nf = 0; nf < 16; nf++)
            acc[nf][0] = acc[nf][1] = acc[nf][2] = acc[nf][3] = 0.0f;

        const uint32_t xa = sb + NP_A + ((m0 + lr16) * APITCH + lc16) * 2;
        #pragma unroll
        for (int half = 0; half < 2; half++) {
            const uint32_t wa = sb + (half ? NP_BL : NP_BH)
                              + ((cgn * 128 + lr8) * APITCH + lc8) * 2;
            #pragma unroll
            for (int kf = 0; kf < 4; kf++) {
                uint32_t a0, a1, a2, a3;
                LDSM_X4(a0, a1, a2, a3, xa + kf * 32);
                #pragma unroll
                for (int nf = 0; nf < 16; nf++) {
                    uint32_t b0, b1;
                    LDSM_X2(b0, b1, wa + (nf * 8 * APITCH + kf * 16) * 2);
                    MMA_F16(acc[nf][0], acc[nf][1], acc[nf][2], acc[nf][3],
                            a0, a1, a2, a3, b0, b1);
                }
            }
        }
        // store U (fp16)
        {
            int nlo = base + m0 + qr, nhi = nlo + 8;
            #pragma unroll
            for (int nf = 0; nf < 16; nf++) {
                int n = cgn * 128 + nf * 8 + qc;
                uint32_t plo, phi;
                CVT_F16X2(plo, acc[nf][0], acc[nf][1]);
                CVT_F16X2(phi, acc[nf][2], acc[nf][3]);
                if (nlo < N_NODES_C) *(uint32_t*)(g_u + (size_t)nlo * UW + n) = plo;
                if (nhi < N_NODES_C) *(uint32_t*)(g_u + (size_t)nhi * UW + n) = phi;
            }
        }
        __syncthreads();
    }
}

// ---------------- edge kernel: ea-GEMM + U-adds + silu + GEMM2 + scatter ----------------
// 8 independent warp-pair pipelines per CTA; pairwise named barriers only.
extern __shared__ char lsm[];

__global__ __launch_bounds__(LYR_THREADS, 1)
void k_layer(const int* __restrict__ ei,
             const float* __restrict__ W1, const float* __restrict__ b1,
             const float* __restrict__ W2, const float* __restrict__ b2) {
    char* sm = lsm;
    const uint32_t sb = smem_u32(sm);
    const int tid = threadIdx.x;
    const int wid = tid >> 5;
    const int lane = tid & 31;

    float* sB1 = (float*)(sm + OFF_B1);
    float* sB2 = (float*)(sm + OFF_B2);

    // W1g = W1 rows 128..159 -> [128 n][EPITCH k], hi/lo
    for (int i = tid; i < 128 * EDIM; i += LYR_THREADS) {
        int n = i >> 5, k = i & 31;
        float v = W1[(128 + k) * HID + n];
        __half hi = __float2half_rn(v);
        __half lo = __float2half_rn(v - __half2float(hi));
        *(__half*)(sm + OFF_WGH + (n * EPITCH + k) * 2) = hi;
        *(__half*)(sm + OFF_WGL + (n * EPITCH + k) * 2) = lo;
    }
    // W2 -> [64 n][HPITCH k], hi/lo
    for (int i = tid; i < 64 * HID; i += LYR_THREADS) {
        int n = i >> 7, k = i & 127;
        float v = W2[k * DIM + n];
        __half hi = __float2half_rn(v);
        __half lo = __float2half_rn(v - __half2float(hi));
        *(__half*)(sm + OFF_W2H + (n * HPITCH + k) * 2) = hi;
        *(__half*)(sm + OFF_W2L + (n * HPITCH + k) * 2) = lo;
    }
    if (tid < HID) sB1[tid] = b1[tid];
    if (tid < DIM) sB2[tid] = b2[tid];

    const int* src = ei;
    const int* dst = ei + N_EDGES_C;

    const int q  = wid & 7;        // pair index / row strip
    const int m0 = q * 16;
    const int cg = wid >> 3;       // 0/1 column group
    const int lr16 = lane & 15;
    const int lc16 = (lane >> 4) * 8;
    const int lr8  = lane & 7;
    const int lc8  = ((lane >> 3) & 1) * 8;
    const int qr   = lane >> 2;
    const int qc   = (lane & 3) * 2;

    // pair-local edge-attr staging: 64 threads cover 16 rows x 4 quarters
    const int pairtid = cg * 32 + lane;   // 0..63
    const int el = pairtid >> 2;          // 0..15 (row within strip)
    const int pq = pairtid & 3;           // quarter (8 halves)
    const int erow = m0 + el;             // row within tile (only rows of own strip)

    // prologue: stage tile0's edge attrs (own strip rows only)
    int tile = blockIdx.x;
    {
        int e0 = tile * TILE_E;
        int valid = min(TILE_E, N_EDGES_C - e0);
        if (erow < valid) {
            uint4 v = *(const uint4*)(g_eb + (size_t)(e0 + erow) * EDIM + pq * 8);
            *(uint4*)(sm + OFF_E + (erow * EPITCH + pq * 8) * 2) = v;
        }
    }
    __syncthreads();   // weights + biases + tile0 sE all visible

    for (; tile < NT_CEIL; tile += LYR_GRID) {
        const int e0 = tile * TILE_E;
        const int valid = min(TILE_E, N_EDGES_C - e0);
        const int tnext = tile + LYR_GRID;
        const int e0n = tnext * TILE_E;
        const int validn = (tnext < NT_CEIL) ? min(TILE_E, N_EDGES_C - e0n) : 0;

        // row indices for this thread's two rows
        const int mlo = m0 + qr, mhi = mlo + 8;
        const bool vlo = mlo < valid, vhi = mhi < valid;
        const int dlo = vlo ? dst[e0 + mlo] : 0;
        const int dhi = vhi ? dst[e0 + mhi] : 0;
        const int slo = vlo ? src[e0 + mlo] : 0;
        const int shi = vhi ? src[e0 + mhi] : 0;

        // ---- issue U gather loads (hidden under ea-GEMM) ----
        uint32_t ud0[8], ud1[8], us0[8], us1[8];
        {
            const __half* pd0 = g_u + (size_t)dlo * UW + cg * 64 + qc;
            const __half* pd1 = g_u + (size_t)dhi * UW + cg * 64 + qc;
            const __half* ps0 = g_u + (size_t)slo * UW + 128 + cg * 64 + qc;
            const __half* ps1 = g_u + (size_t)shi * UW + 128 + cg * 64 + qc;
            #pragma unroll
            for (int nf = 0; nf < 8; nf++) {
                ud0[nf] = *(const uint32_t*)(pd0 + nf * 8);
                ud1[nf] = *(const uint32_t*)(pd1 + nf * 8);
                us0[nf] = *(const uint32_t*)(ps0 + nf * 8);
                us1[nf] = *(const uint32_t*)(ps1 + nf * 8);
            }
        }

        // ---- prefetch next tile's edge attrs (own strip rows) ----
        uint4 pfe;
        bool has_pfe = false;
        if (erow < validn) {
            pfe = *(const uint4*)(g_eb + (size_t)(e0n + erow) * EDIM + pq * 8);
            has_pfe = true;
        }

        // ---- ea-GEMM: acc[strip, cg*64..+64] = sE[strip,32] @ (W1g_hi + W1g_lo) ----
        float acc[8][4];
        #pragma unroll
        for (int nf = 0; nf < 8; nf++)
            acc[nf][0] = acc[nf][1] = acc[nf][2] = acc[nf][3] = 0.0f;
        {
            const uint32_t xa = sb + OFF_E + ((m0 + lr16) * EPITCH + lc16) * 2;
            #pragma unroll
            for (int half = 0; half < 2; half++) {
                const uint32_t wa = sb + (half ? OFF_WGL : OFF_WGH)
                                  + ((cg * 64 + lr8) * EPITCH + lc8) * 2;
                #pragma unroll
                for (int kf = 0; kf < 2; kf++) {
                    uint32_t a0, a1, a2, a3;
                    LDSM_X4(a0, a1, a2, a3, xa + kf * 32);
                    #pragma unroll
                    for (int nf = 0; nf < 8; nf++) {
                        uint32_t b0, b1;
                        LDSM_X2(b0, b1, wa + (nf * 8 * EPITCH + kf * 16) * 2);
                        MMA_F16(acc[nf][0], acc[nf][1], acc[nf][2], acc[nf][3],
                                a0, a1, a2, a3, b0, b1);
                    }
                }
            }
        }

        // ---- epilogue1: + u_dst + u_src + bias, silu -> A2 (fp16) ----
        #pragma unroll
        for (int nf = 0; nf < 8; nf++) {
            int n = cg * 64 + nf * 8 + qc;
            float blo = sB1[n], bhi = sB1[n + 1];
            float2 fd0 = __half22float2(*(__half2*)&ud0[nf]);
            float2 fs0 = __half22float2(*(__half2*)&us0[nf]);
            float2 fd1 = __half22float2(*(__half2*)&ud1[nf]);
            float2 fs1 = __half22float2(*(__half2*)&us1[nf]);
            float v0 = acc[nf][0] + fd0.x + fs0.x + blo;
            float v1 = acc[nf][1] + fd0.y + fs0.y + bhi;
            float v2 = acc[nf][2] + fd1.x + fs1.x + blo;
            float v3 = acc[nf][3] + fd1.y + fs1.y + bhi;
            v0 = v0 / (1.0f + __expf(-v0));
            v1 = v1 / (1.0f + __expf(-v1));
            v2 = v2 / (1.0f + __expf(-v2));
            v3 = v3 / (1.0f + __expf(-v3));
            uint32_t plo, phi;
            CVT_F16X2(plo, v0, v1);
            CVT_F16X2(phi, v2, v3);
            *(uint32_t*)(sm + OFF_A2 + (mlo * HPITCH + n) * 2) = plo;
            *(uint32_t*)(sm + OFF_A2 + (mhi * HPITCH + n) * 2) = phi;
        }
        PAIR_BAR(q);   // pair: A2 strip complete (both halves); sE strip consumed

        // ---- store prefetched edge attrs -> sE (next tile, own strip) ----
        if (has_pfe)
            *(uint4*)(sm + OFF_E + (erow * EPITCH + pq * 8) * 2) = pfe;

        // ---- GEMM2: D2[strip, cg*32..+32] = A2[strip,128] @ (W2_hi + W2_lo) ----
        float acc2[4][4];
        #pragma unroll
        for (int nf = 0; nf < 4; nf++)
            acc2[nf][0] = acc2[nf][1] = acc2[nf][2] = acc2[nf][3] = 0.0f;
        {
            const uint32_t aa = sb + OFF_A2 + ((m0 + lr16) * HPITCH + lc16) * 2;
            #pragma unroll
            for (int half = 0; half < 2; half++) {
                const uint32_t wa = sb + (half ? OFF_W2L : OFF_W2H)
                                  + ((cg * 32 + lr8) * HPITCH + lc8) * 2;
                #pragma unroll
                for (int kf = 0; kf < 8; kf++) {
                    uint32_t a0, a1, a2, a3;
                    LDSM_X4(a0, a1, a2, a3, aa + kf * 32);
                    #pragma unroll
                    for (int nf = 0; nf < 4; nf++) {
                        uint32_t b0, b1;
                        LDSM_X2(b0, b1, wa + (nf * 8 * HPITCH + kf * 16) * 2);
                        MMA_F16(acc2[nf][0], acc2[nf][1], acc2[nf][2], acc2[nf][3],
                                a0, a1, a2, a3, b0, b1);
                    }
                }
            }
        }
        // ---- epilogue2: bias + scatter-add ----
        {
            float* plo = g_agg + (size_t)dlo * DIM;
            float* phi = g_agg + (size_t)dhi * DIM;
            #pragma unroll
            for (int nf = 0; nf < 4; nf++) {
                int n = cg * 32 + nf * 8 + qc;
                float blo = sB2[n], bhi = sB2[n + 1];
                if (vlo) red_add_v2(plo + n, acc2[nf][0] + blo, acc2[nf][1] + bhi);
                if (vhi) red_add_v2(phi + n, acc2[nf][2] + blo, acc2[nf][3] + bhi);
            }
        }
        PAIR_BAR(q);   // pair: sE(next) strip visible; A2 strip free
    }
}

// ---------------- pooling (fused final relu update) ----------------
__global__ void k_pool(const int* __restrict__ batch) {
    int n = blockIdx.x * blockDim.x + threadIdx.x;
    if (n >= N_NODES_C) return;
    int b = batch[n];
    const float4* hp = (const float4*)(g_h + (size_t)n * DIM);
    const float4* ap = (const float4*)(g_agg + (size_t)n * DIM);
    float* pp = g_pool + b * DIM;
    #pragma unroll
    for (int q = 0; q < 16; q++) {
        float4 h = hp[q], a = ap[q];
        red_add_v4(pp + q * 4,
                   fmaxf(h.x + a.x, 0.0f), fmaxf(h.y + a.y, 0.0f),
                   fmaxf(h.z + a.z, 0.0f), fmaxf(h.w + a.w, 0.0f));
    }
    atomicAdd(&g_cnt[b], 1.0f);
}

// ---------------- final FC ----------------
__global__ void k_final(const float* __restrict__ fcw, const float* __restrict__ fcb,
                        float* __restrict__ out) {
    int g = threadIdx.x;
    if (g < NGRAPHS) {
        float c = fmaxf(g_cnt[g], 1.0f);
        float inv = 1.0f / c;
        float s = 0.0f;
        #pragma unroll
        for (int d = 0; d < DIM; d++) s += (g_pool[g * DIM + d] * inv) * fcw[d];
        out[g] = s + fcb[0];
    }
}

extern "C" void kernel_launch(void* const* d_in, const int* in_sizes, int n_in,
                              void* d_out, int out_size) {
    const int*   atoms  = (const int*)d_in[0];
    const int*   ei     = (const int*)d_in[1];   // [2, E]: src row then dst row
    const float* coords = (const float*)d_in[2];
    const int*   isrec  = (const int*)d_in[3];
    const int*   batch  = (const int*)d_in[4];
    const float* emb    = (const float*)d_in[5];
    const float* sub    = (const float*)d_in[6];
    const float* W1     = (const float*)d_in[7]; // [4,160,128]
    const float* b1     = (const float*)d_in[8]; // [4,128]
    const float* W2     = (const float*)d_in[9]; // [4,128,64]
    const float* b2     = (const float*)d_in[10];// [4,64]
    const float* fcw    = (const float*)d_in[11];// [64,1]
    const float* fcb    = (const float*)d_in[12];// [1]
    float* out = (float*)d_out;

    cudaFuncSetAttribute(k_layer, cudaFuncAttributeMaxDynamicSharedMemorySize, SMEM_EDGE);
    cudaFuncSetAttribute(k_nodeprep, cudaFuncAttributeMaxDynamicSharedMemorySize, SMEM_NP);

    k_init_nodes<<<(N_NODES_C * DIM + 255) / 256, 256>>>(atoms, emb);
    k_zero_pool<<<16, 256>>>();
    k_edge_attr<<<(N_EDGES_C + 255) / 256, 256>>>(ei, coords, isrec, sub);

    for (int l = 0; l < NLAYERS; l++) {
        k_nodeprep<<<LYR_GRID, LYR_THREADS, SMEM_NP>>>(W1 + (size_t)l * CATD * HID, l > 0);
        k_layer<<<LYR_GRID, LYR_THREADS, SMEM_EDGE>>>(
            ei, W1 + (size_t)l * CATD * HID, b1 + (size_t)l * HID,
            W2 + (size_t)l * HID * DIM, b2 + (size_t)l * DIM);
    }

    k_pool<<<(N_NODES_C + 255) / 256, 256>>>(batch);
    k_final<<<1, 64>>>(fcw, fcb, out);
}